// round 1
// baseline (speedup 1.0000x reference)
#include <cuda_runtime.h>
#include <math.h>

#define N_NODES 20000
#define N_EDGES 640000
#define HDIM    256
#define GN      16
#define OUTD    100
#define ATOMD   118

// ---------------- scratch (static device globals; no runtime allocation) ----
__device__ float g_h  [N_NODES * HDIM];
__device__ float g_hs [N_NODES * HDIM];
__device__ float g_hd [N_NODES * HDIM];
__device__ float g_rst[N_NODES * HDIM];
__device__ float g_w  [N_EDGES];
__device__ float g_S1 [N_NODES];
__device__ float g_Swr[N_NODES];
__device__ float g_uv [2 * HDIM];
__device__ float g_feat[GN * HDIM];
__device__ int   g_cnt [N_NODES + 1];
__device__ int   g_offs[N_NODES + 1];
__device__ int   g_wp  [N_NODES];
__device__ int   g_csr [N_EDGES];

// ---------------- small utility kernels -------------------------------------
__global__ void zero_pre_kernel(int N) {
    int stride = gridDim.x * blockDim.x;
    int i = blockIdx.x * blockDim.x + threadIdx.x;
    for (int t = i; t < N + 1; t += stride) g_cnt[t] = 0;
    for (int t = i; t < GN * HDIM; t += stride) g_feat[t] = 0.f;
}

__global__ void hist_kernel(const int* __restrict__ dst, int E) {
    int e = blockIdx.x * blockDim.x + threadIdx.x;
    if (e < E) atomicAdd(&g_cnt[dst[e]], 1);
}

// single-block exclusive scan over g_cnt -> g_offs (and copy to g_wp)
__global__ void scan_kernel(int N) {
    __shared__ int partial[1024];
    int t = threadIdx.x;
    int per = (N + 1023) / 1024;
    int start = t * per;
    int stop  = min(start + per, N);
    int sum = 0;
    for (int i = start; i < stop; i++) sum += g_cnt[i];
    partial[t] = sum;
    __syncthreads();
    for (int d = 1; d < 1024; d <<= 1) {
        int v = (t >= d) ? partial[t - d] : 0;
        __syncthreads();
        partial[t] += v;
        __syncthreads();
    }
    int run = (t == 0) ? 0 : partial[t - 1];
    for (int i = start; i < stop; i++) {
        g_offs[i] = run;
        g_wp[i]   = run;
        run += g_cnt[i];
    }
    if (t == 1023) g_offs[N] = partial[1023];
}

__global__ void fill_kernel(const int* __restrict__ dst, int E) {
    int e = blockIdx.x * blockDim.x + threadIdx.x;
    if (e < E) {
        int pos = atomicAdd(&g_wp[dst[e]], 1);
        g_csr[pos] = e;
    }
}

__global__ void layer_zero_kernel(int N) {
    int i = blockIdx.x * blockDim.x + threadIdx.x;
    if (i < N) { g_S1[i] = 0.f; g_Swr[i] = 0.f; }
}

// c-path of node init: g_hd[n][j] = sum_{k<3} coord[n][k] * W_coord[k][j] + b_coord[j]
__global__ void coord_kernel(const float* __restrict__ coord,
                             const float* __restrict__ Wc,
                             const float* __restrict__ bc, int N) {
    int idx = blockIdx.x * blockDim.x + threadIdx.x;
    if (idx >= N * HDIM) return;
    int n = idx >> 8;
    int j = idx & 255;
    float c0 = coord[n * 3 + 0], c1 = coord[n * 3 + 1], c2 = coord[n * 3 + 2];
    g_hd[idx] = c0 * Wc[j] + c1 * Wc[HDIM + j] + c2 * Wc[2 * HDIM + j] + bc[j];
}

// u[j] = sum_k W_edge[k]*We[k][j] ; vp[j] = sum_k b_edge[k]*We[k][j] + b_agg_l[j]
__global__ void uv_kernel(const float* __restrict__ We,
                          const float* __restrict__ Wedge,
                          const float* __restrict__ bedge,
                          const float* __restrict__ bagg_l) {
    int j = threadIdx.x;
    float u = 0.f, v = 0.f;
    for (int k = 0; k < HDIM; k++) {
        float we = We[k * HDIM + j];
        u += Wedge[k] * we;
        v += bedge[k] * we;
    }
    g_uv[j] = u;
    g_uv[HDIM + j] = v + bagg_l[j];
}

// per-edge weight w = exp(log(r)*exp_l) and scalar segment sums
__global__ void edge_w_kernel(const float* __restrict__ radius,
                              const int* __restrict__ dst,
                              const float* __restrict__ exp_l, int l, int E) {
    int e = blockIdx.x * blockDim.x + threadIdx.x;
    if (e >= E) return;
    float r = radius[e];
    float w = expf(logf(r) * exp_l[l]);
    g_w[e] = w;
    int d = dst[e];
    atomicAdd(&g_S1[d],  w);
    atomicAdd(&g_Swr[d], w * r);
}

// per-node aggregation (CSR gather) fused with residual:
// rst[n][j] = (1+eps)*h + sum_e w*hs[src] + S1*(hd[n][j]+vp[j]) + Swr*u[j]
__global__ void agg_kernel(const int* __restrict__ src,
                           const float* __restrict__ eps_l, int l, int N) {
    int n = blockIdx.x;
    if (n >= N) return;
    int j = threadIdx.x;
    __shared__ int   ssrc[256];
    __shared__ float sw[256];
    int beg = g_offs[n], end = g_offs[n + 1];
    float acc = 0.f;
    for (int base = beg; base < end; base += 256) {
        int p = base + j;
        if (p < end) {
            int e = g_csr[p];
            ssrc[j] = src[e];
            sw[j]   = g_w[e];
        }
        __syncthreads();
        int cnt = min(256, end - base);
        for (int q = 0; q < cnt; q++)
            acc += sw[q] * g_hs[ssrc[q] * HDIM + j];
        __syncthreads();
    }
    float s1 = g_S1[n], swr = g_Swr[n];
    float u = g_uv[j], vp = g_uv[HDIM + j];
    int idx = n * HDIM + j;
    float val = (1.f + eps_l[l]) * g_h[idx] + acc + s1 * (g_hd[idx] + vp) + swr * u;
    g_rst[idx] = val;
}

// h = ga * sigmoid(gb)
__global__ void glu_kernel(int N) {
    int i = blockIdx.x * blockDim.x + threadIdx.x;
    if (i >= N * HDIM) return;
    float ga = g_hs[i], gb = g_hd[i];
    g_h[i] = ga * (1.f / (1.f + expf(-gb)));
}

// masked segment-sum over sorted graph_id -> g_feat
__global__ void segsum_kernel(const int* __restrict__ mask,
                              const int* __restrict__ gid, int N) {
    int j  = threadIdx.x;
    int n0 = blockIdx.x * 128;
    if (n0 >= N) return;
    int n1 = min(n0 + 128, N);
    float acc = 0.f;
    int curg = gid[n0];
    for (int n = n0; n < n1; n++) {
        int g = gid[n];
        if (g != curg) {
            atomicAdd(&g_feat[curg * HDIM + j], acc);
            acc = 0.f;
            curg = g;
        }
        if (mask[n]) acc += g_h[n * HDIM + j];
    }
    atomicAdd(&g_feat[curg * HDIM + j], acc);
}

// out[g][o] = sigmoid((feat[g]/N) @ W_mlp + b_mlp)
__global__ void mlp_kernel(const float* __restrict__ Wm,
                           const float* __restrict__ bm,
                           float* __restrict__ out, float invN) {
    int g = blockIdx.x;
    int o = threadIdx.x;
    if (o >= OUTD) return;
    float s = 0.f;
    for (int j = 0; j < HDIM; j++)
        s += g_feat[g * HDIM + j] * Wm[j * OUTD + o];
    s = s * invN + bm[o];
    out[g * OUTD + o] = 1.f / (1.f + expf(-s));
}

// ---------------- SGEMM: C[M,256] = A[M,K] @ B[K,256] (+bias) (+=C) ---------
// 128x128 block tile, BK=8, 8x8 per-thread microtile, 256 threads.
__global__ __launch_bounds__(256, 2)
void sgemm256(const float* __restrict__ A, int lda, int M, int K,
              const float* __restrict__ B,
              float* __restrict__ C,
              const float* __restrict__ bias, int accum) {
    const int BM = 128, BN = 128, BK = 8;
    __shared__ float As[BK][BM];
    __shared__ float Bs[BK][BN];

    int m0 = blockIdx.x * BM;
    int n0 = blockIdx.y * BN;
    int tid = threadIdx.x;
    int tx = tid & 15;       // 0..15 -> output col group
    int ty = tid >> 4;       // 0..15 -> output row group

    // A-load mapping: each thread loads 4 scalars (row ra, cols ca..ca+3)
    int ra = tid >> 1;          // 0..127
    int ca = (tid & 1) * 4;     // 0 or 4
    // B-load mapping: each thread loads one float4
    int kr = tid >> 5;          // 0..7
    int nb = (tid & 31) * 4;    // 0..124

    float acc[8][8];
#pragma unroll
    for (int i = 0; i < 8; i++)
#pragma unroll
        for (int j = 0; j < 8; j++) acc[i][j] = 0.f;

    for (int k0 = 0; k0 < K; k0 += BK) {
        // load A tile (transposed into As[k][m]) with bounds guards
        int mm = m0 + ra;
#pragma unroll
        for (int i = 0; i < 4; i++) {
            int kk = k0 + ca + i;
            float v = 0.f;
            if (mm < M && kk < K) v = A[(size_t)mm * lda + kk];
            As[ca + i][ra] = v;
        }
        // load B tile (row-major, ldb = 256)
        float4 bv = make_float4(0.f, 0.f, 0.f, 0.f);
        if (k0 + kr < K)
            bv = *reinterpret_cast<const float4*>(&B[(size_t)(k0 + kr) * HDIM + n0 + nb]);
        *reinterpret_cast<float4*>(&Bs[kr][nb]) = bv;
        __syncthreads();

#pragma unroll
        for (int k = 0; k < BK; k++) {
            float a[8], b[8];
            *reinterpret_cast<float4*>(&a[0]) = *reinterpret_cast<float4*>(&As[k][ty * 8]);
            *reinterpret_cast<float4*>(&a[4]) = *reinterpret_cast<float4*>(&As[k][ty * 8 + 4]);
            *reinterpret_cast<float4*>(&b[0]) = *reinterpret_cast<float4*>(&Bs[k][tx * 8]);
            *reinterpret_cast<float4*>(&b[4]) = *reinterpret_cast<float4*>(&Bs[k][tx * 8 + 4]);
#pragma unroll
            for (int i = 0; i < 8; i++)
#pragma unroll
                for (int j = 0; j < 8; j++)
                    acc[i][j] += a[i] * b[j];
        }
        __syncthreads();
    }

    // epilogue
#pragma unroll
    for (int i = 0; i < 8; i++) {
        int mm = m0 + ty * 8 + i;
        if (mm >= M) continue;
#pragma unroll
        for (int j = 0; j < 8; j++) {
            int nn = n0 + tx * 8 + j;
            float v = acc[i][j];
            if (bias)  v += bias[nn];
            size_t ci = (size_t)mm * HDIM + nn;
            if (accum) v += C[ci];
            C[ci] = v;
        }
    }
}

// ---------------- launcher ---------------------------------------------------
extern "C" void kernel_launch(void* const* d_in, const int* in_sizes, int n_in,
                              void* d_out, int out_size) {
    const float* atomic_num = (const float*)d_in[0];
    const float* coord      = (const float*)d_in[1];
    const float* radius     = (const float*)d_in[2];
    const int*   src        = (const int*)  d_in[3];
    const int*   dst        = (const int*)  d_in[4];
    const int*   abs_mask   = (const int*)  d_in[5];
    const int*   graph_id   = (const int*)  d_in[6];
    const float* W_atom     = (const float*)d_in[7];
    const float* b_atom     = (const float*)d_in[8];
    const float* W_coord    = (const float*)d_in[9];
    const float* b_coord    = (const float*)d_in[10];
    const float* W_node     = (const float*)d_in[11];
    const float* b_node     = (const float*)d_in[12];
    const float* W_edge     = (const float*)d_in[13];
    const float* b_edge     = (const float*)d_in[14];
    const float* W_agg      = (const float*)d_in[15];
    const float* b_agg      = (const float*)d_in[16];
    const float* W_glu_a    = (const float*)d_in[17];
    const float* b_glu_a    = (const float*)d_in[18];
    const float* W_glu_b    = (const float*)d_in[19];
    const float* b_glu_b    = (const float*)d_in[20];
    const float* exp_l      = (const float*)d_in[21];
    const float* eps_l      = (const float*)d_in[22];
    const float* W_mlp      = (const float*)d_in[23];
    const float* b_mlp      = (const float*)d_in[24];
    float* out = (float*)d_out;

    int N = in_sizes[5];   // abs_mask count
    int E = in_sizes[2];   // radius count

    float *p_h, *p_hs, *p_hd, *p_rst;
    cudaGetSymbolAddress((void**)&p_h,   g_h);
    cudaGetSymbolAddress((void**)&p_hs,  g_hs);
    cudaGetSymbolAddress((void**)&p_hd,  g_hd);
    cudaGetSymbolAddress((void**)&p_rst, g_rst);

    dim3 ggrid((N + 127) / 128, HDIM / 128);
    int eb = (E + 255) / 256;
    int nhb = (N * HDIM + 255) / 256;

    // CSR build (once per launch)
    zero_pre_kernel<<<80, 256>>>(N);
    hist_kernel<<<eb, 256>>>(dst, E);
    scan_kernel<<<1, 1024>>>(N);
    fill_kernel<<<eb, 256>>>(dst, E);

    // node init: h = [a, c] @ W_node + b_node  == a@Wn1 + c@Wn2 + b
    coord_kernel<<<nhb, 256>>>(coord, W_coord, b_coord, N);
    sgemm256<<<ggrid, 256>>>(atomic_num, ATOMD, N, ATOMD, W_atom, p_hs, b_atom, 0);
    sgemm256<<<ggrid, 256>>>(p_hs, HDIM, N, HDIM, W_node, p_h, b_node, 0);
    sgemm256<<<ggrid, 256>>>(p_hd, HDIM, N, HDIM, W_node + HDIM * HDIM, p_h, 0, 1);

    for (int l = 0; l < 2; l++) {
        const float* Wl = W_agg + (size_t)l * 3 * HDIM * HDIM;
        sgemm256<<<ggrid, 256>>>(p_h, HDIM, N, HDIM, Wl, p_hs, 0, 0);                     // hs = h@Ws
        sgemm256<<<ggrid, 256>>>(p_h, HDIM, N, HDIM, Wl + 2 * HDIM * HDIM, p_hd, 0, 0);   // hd = h@Wd
        uv_kernel<<<1, HDIM>>>(Wl + HDIM * HDIM, W_edge, b_edge, b_agg + l * HDIM);
        layer_zero_kernel<<<(N + 255) / 256, 256>>>(N);
        edge_w_kernel<<<eb, 256>>>(radius, dst, exp_l, l, E);
        agg_kernel<<<N, 256>>>(src, eps_l, l, N);
        sgemm256<<<ggrid, 256>>>(p_rst, HDIM, N, HDIM, W_glu_a + (size_t)l * HDIM * HDIM,
                                 p_hs, b_glu_a + l * HDIM, 0);
        sgemm256<<<ggrid, 256>>>(p_rst, HDIM, N, HDIM, W_glu_b + (size_t)l * HDIM * HDIM,
                                 p_hd, b_glu_b + l * HDIM, 0);
        glu_kernel<<<nhb, 256>>>(N);
    }

    segsum_kernel<<<(N + 127) / 128, HDIM>>>(abs_mask, graph_id, N);
    mlp_kernel<<<GN, 128>>>(W_mlp, b_mlp, out, 1.0f / (float)N);
}

// round 2
// speedup vs baseline: 1.9981x; 1.9981x over previous
#include <cuda_runtime.h>
#include <math.h>

#define N_NODES 20000
#define N_EDGES 640000
#define HDIM    256
#define GN      16
#define OUTD    100
#define ATOMD   118

// ---------------- scratch (static device globals; no runtime allocation) ----
__device__ __align__(16) float g_h  [N_NODES * HDIM];
__device__ __align__(16) float g_hs [N_NODES * HDIM];
__device__ __align__(16) float g_hd [N_NODES * HDIM];
__device__ __align__(16) float g_rst[N_NODES * HDIM];
__device__ __align__(16) float g_uv [2 * HDIM];
__device__ __align__(16) float g_F1 [ATOMD * HDIM];
__device__ __align__(16) float g_F2 [3 * HDIM];
__device__ __align__(16) float g_bf [HDIM];
__device__ __align__(16) float g_feat[GN * HDIM];
__device__ int   g_cnt [N_NODES + 1];
__device__ int   g_offs[N_NODES + 1];
__device__ int   g_wp  [N_NODES];
__device__ int   g_csr [N_EDGES];

// ---------------- CSR build --------------------------------------------------
__global__ void zero_pre_kernel(int N) {
    int stride = gridDim.x * blockDim.x;
    int i = blockIdx.x * blockDim.x + threadIdx.x;
    for (int t = i; t < N + 1; t += stride) g_cnt[t] = 0;
    for (int t = i; t < GN * HDIM; t += stride) g_feat[t] = 0.f;
}

__global__ void hist_kernel(const int* __restrict__ dst, int E) {
    int e = blockIdx.x * blockDim.x + threadIdx.x;
    if (e < E) atomicAdd(&g_cnt[dst[e]], 1);
}

__global__ void scan_kernel(int N) {
    __shared__ int partial[1024];
    int t = threadIdx.x;
    int per = (N + 1023) / 1024;
    int start = t * per;
    int stop  = min(start + per, N);
    int sum = 0;
    for (int i = start; i < stop; i++) sum += g_cnt[i];
    partial[t] = sum;
    __syncthreads();
    for (int d = 1; d < 1024; d <<= 1) {
        int v = (t >= d) ? partial[t - d] : 0;
        __syncthreads();
        partial[t] += v;
        __syncthreads();
    }
    int run = (t == 0) ? 0 : partial[t - 1];
    for (int i = start; i < stop; i++) {
        g_offs[i] = run;
        g_wp[i]   = run;
        run += g_cnt[i];
    }
    if (t == 1023) g_offs[N] = partial[1023];
}

__global__ void fill_kernel(const int* __restrict__ dst, int E) {
    int e = blockIdx.x * blockDim.x + threadIdx.x;
    if (e < E) {
        int pos = atomicAdd(&g_wp[dst[e]], 1);
        g_csr[pos] = e;
    }
}

// ---------------- weight folding ---------------------------------------------
// F2[i][j] = sum_h W_coord[i][h] * W_node[256+h][j]   (i<3)
// bf[j]    = sum_h b_atom[h]*W_node[h][j] + sum_h b_coord[h]*W_node[256+h][j] + b_node[j]
__global__ void fold_small_kernel(const float* __restrict__ Wc,
                                  const float* __restrict__ Wn,
                                  const float* __restrict__ ba,
                                  const float* __restrict__ bc,
                                  const float* __restrict__ bn) {
    int j = threadIdx.x;
    float f0 = 0.f, f1 = 0.f, f2 = 0.f, bias = 0.f;
    for (int h = 0; h < HDIM; h++) {
        float wtop = Wn[h * HDIM + j];
        float wbot = Wn[(HDIM + h) * HDIM + j];
        f0 += Wc[0 * HDIM + h] * wbot;
        f1 += Wc[1 * HDIM + h] * wbot;
        f2 += Wc[2 * HDIM + h] * wbot;
        bias += ba[h] * wtop + bc[h] * wbot;
    }
    g_F2[0 * HDIM + j] = f0;
    g_F2[1 * HDIM + j] = f1;
    g_F2[2 * HDIM + j] = f2;
    g_bf[j] = bias + bn[j];
}

// g_h[n][j] = coord[n]·F2[:,j] + bf[j]
__global__ void coord_init_kernel(const float* __restrict__ coord, int N) {
    int idx = blockIdx.x * blockDim.x + threadIdx.x;
    if (idx >= N * HDIM) return;
    int n = idx >> 8;
    int j = idx & 255;
    float c0 = coord[n * 3 + 0], c1 = coord[n * 3 + 1], c2 = coord[n * 3 + 2];
    g_h[idx] = c0 * g_F2[j] + c1 * g_F2[HDIM + j] + c2 * g_F2[2 * HDIM + j] + g_bf[j];
}

// u[j] = sum_k W_edge[k]*We[k][j] ; vp[j] = sum_k b_edge[k]*We[k][j] + b_agg_l[j]
__global__ void uv_kernel(const float* __restrict__ We,
                          const float* __restrict__ Wedge,
                          const float* __restrict__ bedge,
                          const float* __restrict__ bagg_l) {
    int j = threadIdx.x;
    float u = 0.f, v = 0.f;
    for (int k = 0; k < HDIM; k++) {
        float we = We[k * HDIM + j];
        u += Wedge[k] * we;
        v += bedge[k] * we;
    }
    g_uv[j] = u;
    g_uv[HDIM + j] = v + bagg_l[j];
}

// ---------------- warp-per-node aggregation (fused edge weights + residual) --
// rst[n][:] = (1+eps)*h[n] + sum_e w_e*hs[src_e] + S1*(hd[n]+vp) + Swr*u
__global__ void agg_kernel(const int* __restrict__ src,
                           const float* __restrict__ radius,
                           const float* __restrict__ exp_l,
                           const float* __restrict__ eps_l, int l, int N) {
    int warp = (blockIdx.x * blockDim.x + threadIdx.x) >> 5;
    int lane = threadIdx.x & 31;
    if (warp >= N) return;
    float el = __ldg(&exp_l[l]);
    int beg = g_offs[warp], end = g_offs[warp + 1];
    float4 acc0 = make_float4(0.f, 0.f, 0.f, 0.f);
    float4 acc1 = make_float4(0.f, 0.f, 0.f, 0.f);
    float s1 = 0.f, swr = 0.f;
    for (int base = beg; base < end; base += 32) {
        int p = base + lane;
        int s = 0;
        float w = 0.f;
        if (p < end) {
            int e = g_csr[p];
            s = src[e];
            float r = radius[e];
            w = __expf(__logf(r) * el);
            s1 += w;
            swr += w * r;
        }
        int cnt = min(32, end - base);
        for (int q = 0; q < cnt; q++) {
            int   sq = __shfl_sync(0xffffffffu, s, q);
            float wq = __shfl_sync(0xffffffffu, w, q);
            const float4* row = (const float4*)(g_hs + (size_t)sq * HDIM);
            float4 v0 = row[lane * 2];
            float4 v1 = row[lane * 2 + 1];
            acc0.x += wq * v0.x; acc0.y += wq * v0.y;
            acc0.z += wq * v0.z; acc0.w += wq * v0.w;
            acc1.x += wq * v1.x; acc1.y += wq * v1.y;
            acc1.z += wq * v1.z; acc1.w += wq * v1.w;
        }
    }
#pragma unroll
    for (int off = 16; off; off >>= 1) {
        s1  += __shfl_xor_sync(0xffffffffu, s1, off);
        swr += __shfl_xor_sync(0xffffffffu, swr, off);
    }
    float ep = 1.f + __ldg(&eps_l[l]);
    int j0 = lane * 8;
    float4 u0  = *(const float4*)(g_uv + j0);
    float4 u1  = *(const float4*)(g_uv + j0 + 4);
    float4 vp0 = *(const float4*)(g_uv + HDIM + j0);
    float4 vp1 = *(const float4*)(g_uv + HDIM + j0 + 4);
    size_t idx = (size_t)warp * HDIM + j0;
    float4 h0  = *(const float4*)(g_h + idx);
    float4 h1  = *(const float4*)(g_h + idx + 4);
    float4 d0  = *(const float4*)(g_hd + idx);
    float4 d1  = *(const float4*)(g_hd + idx + 4);
    float4 r0, r1;
    r0.x = ep * h0.x + acc0.x + s1 * (d0.x + vp0.x) + swr * u0.x;
    r0.y = ep * h0.y + acc0.y + s1 * (d0.y + vp0.y) + swr * u0.y;
    r0.z = ep * h0.z + acc0.z + s1 * (d0.z + vp0.z) + swr * u0.z;
    r0.w = ep * h0.w + acc0.w + s1 * (d0.w + vp0.w) + swr * u0.w;
    r1.x = ep * h1.x + acc1.x + s1 * (d1.x + vp1.x) + swr * u1.x;
    r1.y = ep * h1.y + acc1.y + s1 * (d1.y + vp1.y) + swr * u1.y;
    r1.z = ep * h1.z + acc1.z + s1 * (d1.z + vp1.z) + swr * u1.z;
    r1.w = ep * h1.w + acc1.w + s1 * (d1.w + vp1.w) + swr * u1.w;
    *(float4*)(g_rst + idx)     = r0;
    *(float4*)(g_rst + idx + 4) = r1;
}

// h = ga * sigmoid(gb)
__global__ void glu_kernel(int N) {
    int i = blockIdx.x * blockDim.x + threadIdx.x;
    if (i >= N * HDIM) return;
    float ga = g_hs[i], gb = g_hd[i];
    g_h[i] = ga * (1.f / (1.f + __expf(-gb)));
}

// masked segment-sum over sorted graph_id -> g_feat
__global__ void segsum_kernel(const int* __restrict__ mask,
                              const int* __restrict__ gid, int N) {
    int j  = threadIdx.x;
    int n0 = blockIdx.x * 128;
    if (n0 >= N) return;
    int n1 = min(n0 + 128, N);
    float acc = 0.f;
    int curg = gid[n0];
    for (int n = n0; n < n1; n++) {
        int g = gid[n];
        if (g != curg) {
            atomicAdd(&g_feat[curg * HDIM + j], acc);
            acc = 0.f;
            curg = g;
        }
        if (mask[n]) acc += g_h[n * HDIM + j];
    }
    atomicAdd(&g_feat[curg * HDIM + j], acc);
}

__global__ void mlp_kernel(const float* __restrict__ Wm,
                           const float* __restrict__ bm,
                           float* __restrict__ out, float invN) {
    int g = blockIdx.x;
    int o = threadIdx.x;
    if (o >= OUTD) return;
    float s = 0.f;
    for (int j = 0; j < HDIM; j++)
        s += g_feat[g * HDIM + j] * Wm[j * OUTD + o];
    s = s * invN + bm[o];
    out[g * OUTD + o] = 1.f / (1.f + __expf(-s));
}

// ---------------- fast SGEMM pair: C{0,1}[M,256] = A[M,256] @ B{0,1}[256,256]
// 128x128 tile, BK=16, double-buffered smem, register-staged prefetch.
__global__ __launch_bounds__(256, 2)
void sgemm_pair(const float* __restrict__ A, int M,
                const float* __restrict__ B0, const float* __restrict__ B1,
                float* __restrict__ C0, float* __restrict__ C1,
                const float* __restrict__ bias0, const float* __restrict__ bias1) {
    const float* B    = blockIdx.z ? B1 : B0;
    float*       C    = blockIdx.z ? C1 : C0;
    const float* bias = blockIdx.z ? bias1 : bias0;

    __shared__ float As[2][16][132];
    __shared__ float Bs[2][16][128];

    int tid = threadIdx.x;
    int m0 = blockIdx.x * 128;
    int n0 = blockIdx.y * 128;
    int tx = tid & 15, ty = tid >> 4;

    int ar = tid >> 2;            // 0..63 ; second half at +64
    int ac = (tid & 3) * 4;
    int bk = tid >> 5;            // 0..7 ; second half at +8
    int bn = (tid & 31) * 4;

    bool aval0 = (m0 + ar) < M;
    bool aval1 = (m0 + ar + 64) < M;
    const float* Arow0 = A + (size_t)(m0 + ar) * HDIM + ac;
    const float* Arow1 = A + (size_t)(m0 + ar + 64) * HDIM + ac;
    const float* Bp0 = B + (size_t)bk * HDIM + n0 + bn;
    const float* Bp1 = B + (size_t)(bk + 8) * HDIM + n0 + bn;

    float4 af0, af1, bf0, bf1;
    const float4 fz = make_float4(0.f, 0.f, 0.f, 0.f);

#define LOADG(k0)                                                   \
    do {                                                            \
        af0 = aval0 ? *(const float4*)(Arow0 + (k0)) : fz;          \
        af1 = aval1 ? *(const float4*)(Arow1 + (k0)) : fz;          \
        bf0 = *(const float4*)(Bp0 + (size_t)(k0) * HDIM);          \
        bf1 = *(const float4*)(Bp1 + (size_t)(k0) * HDIM);          \
    } while (0)

#define STORES(bufi)                                                \
    do {                                                            \
        As[bufi][ac + 0][ar] = af0.x;                               \
        As[bufi][ac + 1][ar] = af0.y;                               \
        As[bufi][ac + 2][ar] = af0.z;                               \
        As[bufi][ac + 3][ar] = af0.w;                               \
        As[bufi][ac + 0][ar + 64] = af1.x;                          \
        As[bufi][ac + 1][ar + 64] = af1.y;                          \
        As[bufi][ac + 2][ar + 64] = af1.z;                          \
        As[bufi][ac + 3][ar + 64] = af1.w;                          \
        *(float4*)&Bs[bufi][bk][bn]     = bf0;                      \
        *(float4*)&Bs[bufi][bk + 8][bn] = bf1;                      \
    } while (0)

    float acc[8][8];
#pragma unroll
    for (int i = 0; i < 8; i++)
#pragma unroll
        for (int j = 0; j < 8; j++) acc[i][j] = 0.f;

    LOADG(0);
    STORES(0);
    __syncthreads();

    int buf = 0;
#pragma unroll 1
    for (int kt = 0; kt < 16; kt++) {
        if (kt < 15) LOADG((kt + 1) * 16);
#pragma unroll
        for (int k = 0; k < 16; k++) {
            float4 a0 = *(const float4*)&As[buf][k][ty * 8];
            float4 a1 = *(const float4*)&As[buf][k][ty * 8 + 4];
            float4 b0 = *(const float4*)&Bs[buf][k][tx * 8];
            float4 b1 = *(const float4*)&Bs[buf][k][tx * 8 + 4];
            float a[8] = {a0.x, a0.y, a0.z, a0.w, a1.x, a1.y, a1.z, a1.w};
            float b[8] = {b0.x, b0.y, b0.z, b0.w, b1.x, b1.y, b1.z, b1.w};
#pragma unroll
            for (int i = 0; i < 8; i++)
#pragma unroll
                for (int j = 0; j < 8; j++)
                    acc[i][j] += a[i] * b[j];
        }
        if (kt < 15) {
            STORES(buf ^ 1);
            __syncthreads();
            buf ^= 1;
        }
    }

    float bv[8];
#pragma unroll
    for (int j = 0; j < 8; j++) bv[j] = bias ? bias[n0 + tx * 8 + j] : 0.f;

#pragma unroll
    for (int i = 0; i < 8; i++) {
        int mm = m0 + ty * 8 + i;
        if (mm >= M) continue;
        float4 o0, o1;
        o0.x = acc[i][0] + bv[0]; o0.y = acc[i][1] + bv[1];
        o0.z = acc[i][2] + bv[2]; o0.w = acc[i][3] + bv[3];
        o1.x = acc[i][4] + bv[4]; o1.y = acc[i][5] + bv[5];
        o1.z = acc[i][6] + bv[6]; o1.w = acc[i][7] + bv[7];
        float* Cp = C + (size_t)mm * HDIM + n0 + tx * 8;
        *(float4*)Cp       = o0;
        *(float4*)(Cp + 4) = o1;
    }
#undef LOADG
#undef STORES
}

// ---------------- generic SGEMM (used for K=118 accumulate path) -------------
__global__ __launch_bounds__(256, 2)
void sgemm256(const float* __restrict__ A, int lda, int M, int K,
              const float* __restrict__ B,
              float* __restrict__ C,
              const float* __restrict__ bias, int accum) {
    const int BM = 128, BN = 128, BK = 8;
    __shared__ float As[BK][BM];
    __shared__ float Bs[BK][BN];

    int m0 = blockIdx.x * BM;
    int n0 = blockIdx.y * BN;
    int tid = threadIdx.x;
    int tx = tid & 15;
    int ty = tid >> 4;
    int ra = tid >> 1;
    int ca = (tid & 1) * 4;
    int kr = tid >> 5;
    int nb = (tid & 31) * 4;

    float acc[8][8];
#pragma unroll
    for (int i = 0; i < 8; i++)
#pragma unroll
        for (int j = 0; j < 8; j++) acc[i][j] = 0.f;

    for (int k0 = 0; k0 < K; k0 += BK) {
        int mm = m0 + ra;
#pragma unroll
        for (int i = 0; i < 4; i++) {
            int kk = k0 + ca + i;
            float v = 0.f;
            if (mm < M && kk < K) v = A[(size_t)mm * lda + kk];
            As[ca + i][ra] = v;
        }
        float4 bvv = make_float4(0.f, 0.f, 0.f, 0.f);
        if (k0 + kr < K)
            bvv = *reinterpret_cast<const float4*>(&B[(size_t)(k0 + kr) * HDIM + n0 + nb]);
        *reinterpret_cast<float4*>(&Bs[kr][nb]) = bvv;
        __syncthreads();

#pragma unroll
        for (int k = 0; k < BK; k++) {
            float a[8], b[8];
            *reinterpret_cast<float4*>(&a[0]) = *reinterpret_cast<float4*>(&As[k][ty * 8]);
            *reinterpret_cast<float4*>(&a[4]) = *reinterpret_cast<float4*>(&As[k][ty * 8 + 4]);
            *reinterpret_cast<float4*>(&b[0]) = *reinterpret_cast<float4*>(&Bs[k][tx * 8]);
            *reinterpret_cast<float4*>(&b[4]) = *reinterpret_cast<float4*>(&Bs[k][tx * 8 + 4]);
#pragma unroll
            for (int i = 0; i < 8; i++)
#pragma unroll
                for (int j = 0; j < 8; j++)
                    acc[i][j] += a[i] * b[j];
        }
        __syncthreads();
    }

#pragma unroll
    for (int i = 0; i < 8; i++) {
        int mm = m0 + ty * 8 + i;
        if (mm >= M) continue;
#pragma unroll
        for (int j = 0; j < 8; j++) {
            int nn = n0 + tx * 8 + j;
            float v = acc[i][j];
            if (bias) v += bias[nn];
            size_t ci = (size_t)mm * HDIM + nn;
            if (accum) v += C[ci];
            C[ci] = v;
        }
    }
}

// ---------------- launcher ---------------------------------------------------
extern "C" void kernel_launch(void* const* d_in, const int* in_sizes, int n_in,
                              void* d_out, int out_size) {
    const float* atomic_num = (const float*)d_in[0];
    const float* coord      = (const float*)d_in[1];
    const float* radius     = (const float*)d_in[2];
    const int*   src        = (const int*)  d_in[3];
    const int*   dst        = (const int*)  d_in[4];
    const int*   abs_mask   = (const int*)  d_in[5];
    const int*   graph_id   = (const int*)  d_in[6];
    const float* W_atom     = (const float*)d_in[7];
    const float* b_atom     = (const float*)d_in[8];
    const float* W_coord    = (const float*)d_in[9];
    const float* b_coord    = (const float*)d_in[10];
    const float* W_node     = (const float*)d_in[11];
    const float* b_node     = (const float*)d_in[12];
    const float* W_edge     = (const float*)d_in[13];
    const float* b_edge     = (const float*)d_in[14];
    const float* W_agg      = (const float*)d_in[15];
    const float* b_agg      = (const float*)d_in[16];
    const float* W_glu_a    = (const float*)d_in[17];
    const float* b_glu_a    = (const float*)d_in[18];
    const float* W_glu_b    = (const float*)d_in[19];
    const float* b_glu_b    = (const float*)d_in[20];
    const float* exp_l      = (const float*)d_in[21];
    const float* eps_l      = (const float*)d_in[22];
    const float* W_mlp      = (const float*)d_in[23];
    const float* b_mlp      = (const float*)d_in[24];
    float* out = (float*)d_out;

    int N = in_sizes[5];
    int E = in_sizes[2];

    float *p_h, *p_hs, *p_hd, *p_rst, *p_F1;
    cudaGetSymbolAddress((void**)&p_h,   g_h);
    cudaGetSymbolAddress((void**)&p_hs,  g_hs);
    cudaGetSymbolAddress((void**)&p_hd,  g_hd);
    cudaGetSymbolAddress((void**)&p_rst, g_rst);
    cudaGetSymbolAddress((void**)&p_F1,  g_F1);

    int mb = (N + 127) / 128;
    dim3 gpair(mb, 2, 2);
    dim3 gfold(1, 2, 1);
    dim3 ggen(mb, 2);
    int eb = (E + 255) / 256;
    int nhb = (N * HDIM + 255) / 256;
    int aggb = (N + 7) / 8;

    // CSR build
    zero_pre_kernel<<<80, 256>>>(N);
    hist_kernel<<<eb, 256>>>(dst, E);
    scan_kernel<<<1, 1024>>>(N);
    fill_kernel<<<eb, 256>>>(dst, E);

    // weight folding + node init
    sgemm_pair<<<gfold, 256>>>(W_atom, ATOMD, W_node, W_node, p_F1, p_F1,
                               nullptr, nullptr);                  // F1 = Wa @ Wn_top
    fold_small_kernel<<<1, HDIM>>>(W_coord, W_node, b_atom, b_coord, b_node);
    coord_init_kernel<<<nhb, 256>>>(coord, N);                     // h = coord-part + bias
    sgemm256<<<ggen, 256>>>(atomic_num, ATOMD, N, ATOMD, p_F1, p_h, nullptr, 1); // h += x@F1

    for (int l = 0; l < 2; l++) {
        const float* Wl = W_agg + (size_t)l * 3 * HDIM * HDIM;
        sgemm_pair<<<gpair, 256>>>(p_h, N, Wl, Wl + 2 * HDIM * HDIM,
                                   p_hs, p_hd, nullptr, nullptr);  // hs=h@Ws, hd=h@Wd
        uv_kernel<<<1, HDIM>>>(Wl + HDIM * HDIM, W_edge, b_edge, b_agg + l * HDIM);
        agg_kernel<<<aggb, 256>>>(src, radius, exp_l, eps_l, l, N);
        sgemm_pair<<<gpair, 256>>>(p_rst, N,
                                   W_glu_a + (size_t)l * HDIM * HDIM,
                                   W_glu_b + (size_t)l * HDIM * HDIM,
                                   p_hs, p_hd,
                                   b_glu_a + l * HDIM, b_glu_b + l * HDIM);
        glu_kernel<<<nhb, 256>>>(N);
    }

    segsum_kernel<<<(N + 127) / 128, HDIM>>>(abs_mask, graph_id, N);
    mlp_kernel<<<GN, 128>>>(W_mlp, b_mlp, out, 1.0f / (float)N);
}

// round 6
// speedup vs baseline: 2.7436x; 1.3731x over previous
#include <cuda_runtime.h>
#include <cuda_bf16.h>
#include <stdint.h>
#include <cstdint>
#include <math.h>

#define N_NODES 20000
#define N_EDGES 640000
#define HDIM    256
#define GN      16
#define OUTD    100
#define ATOMD   118
#define HH      (HDIM * HDIM)

// ---------------- scratch ----------------------------------------------------
__device__ __align__(16) float g_h  [N_NODES * HDIM];
__device__ __align__(16) float g_hs [N_NODES * HDIM];
__device__ __align__(16) float g_hd [N_NODES * HDIM];
__device__ __align__(16) float g_uv [2 * HDIM];
__device__ __align__(16) float g_F1 [ATOMD * HDIM];
__device__ __align__(16) float g_F2 [3 * HDIM];
__device__ __align__(16) float g_bf [HDIM];
__device__ __align__(16) float g_feat[GN * HDIM];
__device__ int   g_cnt [N_NODES + 1];
__device__ int   g_offs[N_NODES + 1];
__device__ int   g_wp  [N_NODES];
__device__ int   g_csr [N_EDGES];
// bf16 split operands
__device__ __align__(16) __nv_bfloat16 g_xa_hi[N_NODES * 128];
__device__ __align__(16) __nv_bfloat16 g_xa_lo[N_NODES * 128];
__device__ __align__(16) __nv_bfloat16 g_h_hi [N_NODES * HDIM];
__device__ __align__(16) __nv_bfloat16 g_h_lo [N_NODES * HDIM];
__device__ __align__(16) __nv_bfloat16 g_r_hi [N_NODES * HDIM];
__device__ __align__(16) __nv_bfloat16 g_r_lo [N_NODES * HDIM];
__device__ __align__(16) __nv_bfloat16 g_Bt_hi[8 * HH];
__device__ __align__(16) __nv_bfloat16 g_Bt_lo[8 * HH];
__device__ __align__(16) __nv_bfloat16 g_F1t_hi[HDIM * 128];
__device__ __align__(16) __nv_bfloat16 g_F1t_lo[HDIM * 128];

// ---------------- mma.sync helpers (sm_80+ PTX, legal on compute_100) --------
__device__ __forceinline__ uint32_t smem_to_u32(const void* p) {
    uint32_t a;
    asm("{ .reg .u64 t; cvta.to.shared.u64 t, %1; cvt.u32.u64 %0, t; }" : "=r"(a) : "l"(p));
    return a;
}
__device__ __forceinline__ void ldsm4(uint32_t* r, uint32_t addr) {
    asm volatile("ldmatrix.sync.aligned.m8n8.x4.shared.b16 {%0,%1,%2,%3}, [%4];"
                 : "=r"(r[0]), "=r"(r[1]), "=r"(r[2]), "=r"(r[3]) : "r"(addr));
}
__device__ __forceinline__ void mma16816(float* c, const uint32_t* a, uint32_t b0, uint32_t b1) {
    asm volatile("mma.sync.aligned.m16n8k16.row.col.f32.bf16.bf16.f32 "
                 "{%0,%1,%2,%3}, {%4,%5,%6,%7}, {%8,%9}, {%0,%1,%2,%3};"
                 : "+f"(c[0]), "+f"(c[1]), "+f"(c[2]), "+f"(c[3])
                 : "r"(a[0]), "r"(a[1]), "r"(a[2]), "r"(a[3]), "r"(b0), "r"(b1));
}

// ---------------- CSR build --------------------------------------------------
__global__ void zero_pre_kernel(int N) {
    int stride = gridDim.x * blockDim.x;
    int i = blockIdx.x * blockDim.x + threadIdx.x;
    for (int t = i; t < N + 1; t += stride) g_cnt[t] = 0;
    for (int t = i; t < GN * HDIM; t += stride) g_feat[t] = 0.f;
}
__global__ void hist_kernel(const int* __restrict__ dst, int E) {
    int e = blockIdx.x * blockDim.x + threadIdx.x;
    if (e < E) atomicAdd(&g_cnt[dst[e]], 1);
}
__global__ void scan_kernel(int N) {
    __shared__ int partial[1024];
    int t = threadIdx.x;
    int per = (N + 1023) / 1024;
    int start = t * per;
    int stop  = min(start + per, N);
    int sum = 0;
    for (int i = start; i < stop; i++) sum += g_cnt[i];
    partial[t] = sum;
    __syncthreads();
    for (int d = 1; d < 1024; d <<= 1) {
        int v = (t >= d) ? partial[t - d] : 0;
        __syncthreads();
        partial[t] += v;
        __syncthreads();
    }
    int run = (t == 0) ? 0 : partial[t - 1];
    for (int i = start; i < stop; i++) {
        g_offs[i] = run;
        g_wp[i]   = run;
        run += g_cnt[i];
    }
    if (t == 1023) g_offs[N] = partial[1023];
}
__global__ void fill_kernel(const int* __restrict__ dst, int E) {
    int e = blockIdx.x * blockDim.x + threadIdx.x;
    if (e < E) {
        int pos = atomicAdd(&g_wp[dst[e]], 1);
        g_csr[pos] = e;
    }
}

// ---------------- weight folding / conversions -------------------------------
__global__ void fold_small_kernel(const float* __restrict__ Wc,
                                  const float* __restrict__ Wn,
                                  const float* __restrict__ ba,
                                  const float* __restrict__ bc,
                                  const float* __restrict__ bn) {
    int j = threadIdx.x;
    float f0 = 0.f, f1 = 0.f, f2 = 0.f, bias = 0.f;
    for (int h = 0; h < HDIM; h++) {
        float wtop = Wn[h * HDIM + j];
        float wbot = Wn[(HDIM + h) * HDIM + j];
        f0 += Wc[0 * HDIM + h] * wbot;
        f1 += Wc[1 * HDIM + h] * wbot;
        f2 += Wc[2 * HDIM + h] * wbot;
        bias += ba[h] * wtop + bc[h] * wbot;
    }
    g_F2[0 * HDIM + j] = f0;
    g_F2[1 * HDIM + j] = f1;
    g_F2[2 * HDIM + j] = f2;
    g_bf[j] = bias + bn[j];
}

__global__ void coord_init_kernel(const float* __restrict__ coord, int N) {
    int idx = blockIdx.x * blockDim.x + threadIdx.x;
    if (idx >= N * HDIM) return;
    int n = idx >> 8;
    int j = idx & 255;
    float c0 = coord[n * 3], c1 = coord[n * 3 + 1], c2 = coord[n * 3 + 2];
    g_hd[idx] = c0 * g_F2[j] + c1 * g_F2[HDIM + j] + c2 * g_F2[2 * HDIM + j] + g_bf[j];
}

__device__ __forceinline__ void split_bf16(float v, __nv_bfloat16& hi, __nv_bfloat16& lo) {
    hi = __float2bfloat16(v);
    lo = __float2bfloat16(v - __bfloat162float(hi));
}

__global__ void conv_x_kernel(const float* __restrict__ x, int N) {
    int e = blockIdx.x * blockDim.x + threadIdx.x;
    if (e >= N * 128) return;
    int n = e >> 7, kk = e & 127;
    float v = (kk < ATOMD) ? x[n * ATOMD + kk] : 0.f;
    __nv_bfloat16 hi, lo;
    split_bf16(v, hi, lo);
    g_xa_hi[e] = hi;
    g_xa_lo[e] = lo;
}

__global__ void conv_wT_kernel(const float* __restrict__ W_agg,
                               const float* __restrict__ W_glu_a,
                               const float* __restrict__ W_glu_b) {
    int z = blockIdx.y;
    const float* src;
    switch (z) {
        case 0: src = W_agg; break;
        case 1: src = W_agg + 2 * HH; break;
        case 2: src = W_agg + 3 * HH; break;
        case 3: src = W_agg + 5 * HH; break;
        case 4: src = W_glu_a; break;
        case 5: src = W_glu_b; break;
        case 6: src = W_glu_a + HH; break;
        default: src = W_glu_b + HH; break;
    }
    int e = blockIdx.x * blockDim.x + threadIdx.x;
    int n = e >> 8, k = e & 255;
    float v = src[k * HDIM + n];
    __nv_bfloat16 hi, lo;
    split_bf16(v, hi, lo);
    g_Bt_hi[z * HH + e] = hi;
    g_Bt_lo[z * HH + e] = lo;
}

__global__ void conv_F1t_kernel() {
    int e = blockIdx.x * blockDim.x + threadIdx.x;
    if (e >= HDIM * 128) return;
    int n = e >> 7, k = e & 127;
    float v = (k < ATOMD) ? g_F1[k * HDIM + n] : 0.f;
    __nv_bfloat16 hi, lo;
    split_bf16(v, hi, lo);
    g_F1t_hi[e] = hi;
    g_F1t_lo[e] = lo;
}

__global__ void uv_kernel(const float* __restrict__ We,
                          const float* __restrict__ Wedge,
                          const float* __restrict__ bedge,
                          const float* __restrict__ bagg_l) {
    int j = threadIdx.x;
    float u = 0.f, v = 0.f;
    for (int k = 0; k < HDIM; k++) {
        float we = We[k * HDIM + j];
        u += Wedge[k] * we;
        v += bedge[k] * we;
    }
    g_uv[j] = u;
    g_uv[HDIM + j] = v + bagg_l[j];
}

// ---------------- warp-per-node aggregation ---------------------------------
__global__ void agg_kernel(const int* __restrict__ src,
                           const float* __restrict__ radius,
                           const float* __restrict__ exp_l,
                           const float* __restrict__ eps_l, int l, int N) {
    int warp = (blockIdx.x * blockDim.x + threadIdx.x) >> 5;
    int lane = threadIdx.x & 31;
    if (warp >= N) return;
    float el = __ldg(&exp_l[l]);
    int beg = g_offs[warp], end = g_offs[warp + 1];
    float4 acc0 = make_float4(0.f, 0.f, 0.f, 0.f);
    float4 acc1 = make_float4(0.f, 0.f, 0.f, 0.f);
    float s1 = 0.f, swr = 0.f;
    for (int base = beg; base < end; base += 32) {
        int p = base + lane;
        int s = 0;
        float w = 0.f;
        if (p < end) {
            int e = g_csr[p];
            s = src[e];
            float r = radius[e];
            w = __expf(__logf(r) * el);
            s1 += w;
            swr += w * r;
        }
        int cnt = min(32, end - base);
        for (int q = 0; q < cnt; q++) {
            int   sq = __shfl_sync(0xffffffffu, s, q);
            float wq = __shfl_sync(0xffffffffu, w, q);
            const float4* row = (const float4*)(g_hs + (size_t)sq * HDIM);
            float4 v0 = row[lane * 2];
            float4 v1 = row[lane * 2 + 1];
            acc0.x += wq * v0.x; acc0.y += wq * v0.y;
            acc0.z += wq * v0.z; acc0.w += wq * v0.w;
            acc1.x += wq * v1.x; acc1.y += wq * v1.y;
            acc1.z += wq * v1.z; acc1.w += wq * v1.w;
        }
    }
#pragma unroll
    for (int off = 16; off; off >>= 1) {
        s1  += __shfl_xor_sync(0xffffffffu, s1, off);
        swr += __shfl_xor_sync(0xffffffffu, swr, off);
    }
    float ep = 1.f + __ldg(&eps_l[l]);
    int j0 = lane * 8;
    float4 u0  = *(const float4*)(g_uv + j0);
    float4 u1  = *(const float4*)(g_uv + j0 + 4);
    float4 vp0 = *(const float4*)(g_uv + HDIM + j0);
    float4 vp1 = *(const float4*)(g_uv + HDIM + j0 + 4);
    size_t idx = (size_t)warp * HDIM + j0;
    float4 h0  = *(const float4*)(g_h + idx);
    float4 h1  = *(const float4*)(g_h + idx + 4);
    float4 d0  = *(const float4*)(g_hd + idx);
    float4 d1  = *(const float4*)(g_hd + idx + 4);
    float v[8];
    v[0] = ep * h0.x + acc0.x + s1 * (d0.x + vp0.x) + swr * u0.x;
    v[1] = ep * h0.y + acc0.y + s1 * (d0.y + vp0.y) + swr * u0.y;
    v[2] = ep * h0.z + acc0.z + s1 * (d0.z + vp0.z) + swr * u0.z;
    v[3] = ep * h0.w + acc0.w + s1 * (d0.w + vp0.w) + swr * u0.w;
    v[4] = ep * h1.x + acc1.x + s1 * (d1.x + vp1.x) + swr * u1.x;
    v[5] = ep * h1.y + acc1.y + s1 * (d1.y + vp1.y) + swr * u1.y;
    v[6] = ep * h1.z + acc1.z + s1 * (d1.z + vp1.z) + swr * u1.z;
    v[7] = ep * h1.w + acc1.w + s1 * (d1.w + vp1.w) + swr * u1.w;
    __nv_bfloat16 hi8[8];
    __nv_bfloat16 lo8[8];
#pragma unroll
    for (int j = 0; j < 8; j++) split_bf16(v[j], hi8[j], lo8[j]);
    *(uint4*)(g_r_hi + idx) = *(uint4*)hi8;
    *(uint4*)(g_r_lo + idx) = *(uint4*)lo8;
}

// h = ga * sigmoid(gb); also write bf16 split of h
__global__ void glu_kernel(int N) {
    int i = blockIdx.x * blockDim.x + threadIdx.x;
    if (i >= N * HDIM) return;
    float ga = g_hs[i], gb = g_hd[i];
    float h = ga * (1.f / (1.f + __expf(-gb)));
    g_h[i] = h;
    __nv_bfloat16 hi, lo;
    split_bf16(h, hi, lo);
    g_h_hi[i] = hi;
    g_h_lo[i] = lo;
}

__global__ void segsum_kernel(const int* __restrict__ mask,
                              const int* __restrict__ gid, int N) {
    int j  = threadIdx.x;
    int n0 = blockIdx.x * 128;
    if (n0 >= N) return;
    int n1 = min(n0 + 128, N);
    float acc = 0.f;
    int curg = gid[n0];
    for (int n = n0; n < n1; n++) {
        int g = gid[n];
        if (g != curg) {
            atomicAdd(&g_feat[curg * HDIM + j], acc);
            acc = 0.f;
            curg = g;
        }
        if (mask[n]) acc += g_h[n * HDIM + j];
    }
    atomicAdd(&g_feat[curg * HDIM + j], acc);
}

__global__ void mlp_kernel(const float* __restrict__ Wm,
                           const float* __restrict__ bm,
                           float* __restrict__ out, float invN) {
    int g = blockIdx.x;
    int o = threadIdx.x;
    if (o >= OUTD) return;
    float s = 0.f;
    for (int j = 0; j < HDIM; j++)
        s += g_feat[g * HDIM + j] * Wm[j * OUTD + o];
    s = s * invN + bm[o];
    out[g * OUTD + o] = 1.f / (1.f + __expf(-s));
}

// ---------------- mma.sync split-bf16 GEMM -----------------------------------
// C[M,256] = (Ahi+Alo) @ Bt^T, 3-term bf16 split on HMMA tensor cores.
// Block: 128x128 tile (grid.y selects n-half), 256 thr = 8 warps of 32x64.
// SMEM: Ah/Al/Bh/Bl double-buffered [2][128][40] bf16 each = 81920 B.
#define TSB 10240            // one stage of one array, bytes (128*40*2)
#define OFF_AL 20480
#define OFF_BH 40960
#define OFF_BL 61440

__global__ __launch_bounds__(256, 2)
void mma_gemm(const __nv_bfloat16* __restrict__ Ahi, const __nv_bfloat16* __restrict__ Alo,
              int M, int Ktot,
              const __nv_bfloat16* __restrict__ Bh0, const __nv_bfloat16* __restrict__ Bl0,
              const __nv_bfloat16* __restrict__ Bh1, const __nv_bfloat16* __restrict__ Bl1,
              float* __restrict__ C0, float* __restrict__ C1,
              const float* __restrict__ bias0, const float* __restrict__ bias1,
              const float* __restrict__ addend,
              __nv_bfloat16* __restrict__ Chi, __nv_bfloat16* __restrict__ Clo) {
    extern __shared__ char smem[];
    const __nv_bfloat16* Bhi = blockIdx.z ? Bh1 : Bh0;
    const __nv_bfloat16* Blo = blockIdx.z ? Bl1 : Bl0;
    float* Cout = blockIdx.z ? C1 : C0;
    const float* bias = blockIdx.z ? bias1 : bias0;

    int tid = threadIdx.x;
    int wid = tid >> 5;
    int lane = tid & 31;
    int warp_m = wid & 3;        // 0..3 -> m offset 0,32,64,96
    int warp_n = wid >> 2;       // 0..1 -> n offset 0,64
    int m0 = blockIdx.x * 128;
    int n0 = blockIdx.y * 128;   // B row base (n index)
    uint32_t sb = smem_to_u32(smem);

    float acc[2][8][4];
#pragma unroll
    for (int a = 0; a < 2; a++)
#pragma unroll
        for (int b = 0; b < 8; b++)
#pragma unroll
            for (int c = 0; c < 4; c++) acc[a][b][c] = 0.f;

    int KT = Ktot >> 5;          // BK=32 stages

    // ldmatrix per-lane row/col pieces
    int lrow = (lane & 7) + ((lane >> 3) & 1) * 8;
    int lcol = (lane >> 4) * 8;

    // ---- stage loader (LDG -> STS) ----
#define LOAD_STAGE(kt, buf)                                                        \
    do {                                                                           \
        int k0 = (kt) * 32;                                                        \
        _Pragma("unroll")                                                          \
        for (int i = 0; i < 2; i++) {                                              \
            int v = tid + i * 256;                                                 \
            int row = v >> 2, kc = (v & 3) * 8;                                    \
            uint4 z = make_uint4(0, 0, 0, 0);                                      \
            bool av = (m0 + row) < M;                                              \
            size_t ao = (size_t)(m0 + row) * Ktot + k0 + kc;                       \
            size_t bo = (size_t)(n0 + row) * Ktot + k0 + kc;                       \
            uint4 va  = av ? *(const uint4*)(Ahi + ao) : z;                        \
            uint4 vl  = av ? *(const uint4*)(Alo + ao) : z;                        \
            uint4 vbh = *(const uint4*)(Bhi + bo);                                 \
            uint4 vbl = *(const uint4*)(Blo + bo);                                 \
            char* d = smem + (buf) * TSB + ((size_t)row * 40 + kc) * 2;            \
            *(uint4*)(d)          = va;                                            \
            *(uint4*)(d + OFF_AL) = vl;                                            \
            *(uint4*)(d + OFF_BH) = vbh;                                           \
            *(uint4*)(d + OFF_BL) = vbl;                                           \
        }                                                                          \
    } while (0)

    LOAD_STAGE(0, 0);
    __syncthreads();

#pragma unroll 1
    for (int kt = 0; kt < KT; kt++) {
        int buf = kt & 1;
        if (kt + 1 < KT) LOAD_STAGE(kt + 1, buf ^ 1);

#pragma unroll
        for (int ks = 0; ks < 2; ks++) {
            int kc = ks * 16 + lcol;
            uint32_t ah[2][4], al[2][4];
#pragma unroll
            for (int mt = 0; mt < 2; mt++) {
                int r = warp_m * 32 + mt * 16 + lrow;
                uint32_t addr = sb + buf * TSB + ((uint32_t)r * 40 + kc) * 2;
                ldsm4(ah[mt], addr);
                ldsm4(al[mt], addr + OFF_AL);
            }
#pragma unroll
            for (int ng = 0; ng < 4; ng++) {
                int r = warp_n * 64 + ng * 16 + lrow;
                uint32_t baddr = sb + buf * TSB + ((uint32_t)r * 40 + kc) * 2 + OFF_BH;
                uint32_t bh[4], bl[4];
                ldsm4(bh, baddr);
                ldsm4(bl, baddr + (OFF_BL - OFF_BH));
#pragma unroll
                for (int mt = 0; mt < 2; mt++) {
                    mma16816(acc[mt][2 * ng],     ah[mt], bh[0], bh[2]);
                    mma16816(acc[mt][2 * ng],     ah[mt], bl[0], bl[2]);
                    mma16816(acc[mt][2 * ng],     al[mt], bh[0], bh[2]);
                    mma16816(acc[mt][2 * ng + 1], ah[mt], bh[1], bh[3]);
                    mma16816(acc[mt][2 * ng + 1], ah[mt], bl[1], bl[3]);
                    mma16816(acc[mt][2 * ng + 1], al[mt], bh[1], bh[3]);
                }
            }
        }
        __syncthreads();
    }

    // ---- epilogue ----
    int gi = lane >> 2;
    int ci = (lane & 3) * 2;
#pragma unroll
    for (int mt = 0; mt < 2; mt++) {
#pragma unroll
        for (int nt = 0; nt < 8; nt++) {
            float* a4 = acc[mt][nt];
            int col = n0 + warp_n * 64 + nt * 8 + ci;
            float b0 = 0.f, b1 = 0.f;
            if (bias) { b0 = __ldg(&bias[col]); b1 = __ldg(&bias[col + 1]); }
#pragma unroll
            for (int half = 0; half < 2; half++) {
                int row = m0 + warp_m * 32 + mt * 16 + gi + half * 8;
                if (row >= M) continue;
                float v0 = a4[half * 2]     + b0;
                float v1 = a4[half * 2 + 1] + b1;
                size_t o = (size_t)row * HDIM + col;
                if (addend) {
                    float2 t = *(const float2*)(addend + o);
                    v0 += t.x; v1 += t.y;
                }
                *(float2*)(Cout + o) = make_float2(v0, v1);
                if (Chi) {
                    __nv_bfloat16 h0, l0, h1, l1;
                    split_bf16(v0, h0, l0);
                    split_bf16(v1, h1, l1);
                    __nv_bfloat162 hv; hv.x = h0; hv.y = h1;
                    __nv_bfloat162 lv; lv.x = l0; lv.y = l1;
                    *(__nv_bfloat162*)(Chi + o) = hv;
                    *(__nv_bfloat162*)(Clo + o) = lv;
                }
            }
        }
    }
#undef LOAD_STAGE
}

// ---------------- small fp32 GEMM for the F1 fold (M=118) --------------------
__global__ __launch_bounds__(256, 2)
void sgemm_pair(const float* __restrict__ A, int M,
                const float* __restrict__ B0, const float* __restrict__ B1,
                float* __restrict__ C0, float* __restrict__ C1,
                const float* __restrict__ bias0, const float* __restrict__ bias1) {
    const float* B    = blockIdx.z ? B1 : B0;
    float*       C    = blockIdx.z ? C1 : C0;
    const float* bias = blockIdx.z ? bias1 : bias0;
    __shared__ float As[2][16][132];
    __shared__ float Bs[2][16][128];
    int tid = threadIdx.x;
    int m0 = blockIdx.x * 128;
    int n0 = blockIdx.y * 128;
    int tx = tid & 15, ty = tid >> 4;
    int ar = tid >> 2;
    int ac = (tid & 3) * 4;
    int bk = tid >> 5;
    int bn = (tid & 31) * 4;
    bool aval0 = (m0 + ar) < M;
    bool aval1 = (m0 + ar + 64) < M;
    const float* Arow0 = A + (size_t)(m0 + ar) * HDIM + ac;
    const float* Arow1 = A + (size_t)(m0 + ar + 64) * HDIM + ac;
    const float* Bp0 = B + (size_t)bk * HDIM + n0 + bn;
    const float* Bp1 = B + (size_t)(bk + 8) * HDIM + n0 + bn;
    float4 af0, af1, bf0, bf1;
    const float4 fz = make_float4(0.f, 0.f, 0.f, 0.f);
#define LOADG(k0) do { \
        af0 = aval0 ? *(const float4*)(Arow0 + (k0)) : fz; \
        af1 = aval1 ? *(const float4*)(Arow1 + (k0)) : fz; \
        bf0 = *(const float4*)(Bp0 + (size_t)(k0) * HDIM); \
        bf1 = *(const float4*)(Bp1 + (size_t)(k0) * HDIM); } while (0)
#define STORES(bufi) do { \
        As[bufi][ac + 0][ar] = af0.x; As[bufi][ac + 1][ar] = af0.y; \
        As[bufi][ac + 2][ar] = af0.z; As[bufi][ac + 3][ar] = af0.w; \
        As[bufi][ac + 0][ar + 64] = af1.x; As[bufi][ac + 1][ar + 64] = af1.y; \
        As[bufi][ac + 2][ar + 64] = af1.z; As[bufi][ac + 3][ar + 64] = af1.w; \
        *(float4*)&Bs[bufi][bk][bn] = bf0; *(float4*)&Bs[bufi][bk + 8][bn] = bf1; } while (0)
    float acc[8][8];
#pragma unroll
    for (int i = 0; i < 8; i++)
#pragma unroll
        for (int j = 0; j < 8; j++) acc[i][j] = 0.f;
    LOADG(0);
    STORES(0);
    __syncthreads();
    int buf = 0;
#pragma unroll 1
    for (int kt = 0; kt < 16; kt++) {
        if (kt < 15) LOADG((kt + 1) * 16);
#pragma unroll
        for (int k = 0; k < 16; k++) {
            float4 a0 = *(const float4*)&As[buf][k][ty * 8];
            float4 a1 = *(const float4*)&As[buf][k][ty * 8 + 4];
            float4 b0 = *(const float4*)&Bs[buf][k][tx * 8];
            float4 b1 = *(const float4*)&Bs[buf][k][tx * 8 + 4];
            float a[8] = {a0.x, a0.y, a0.z, a0.w, a1.x, a1.y, a1.z, a1.w};
            float b[8] = {b0.x, b0.y, b0.z, b0.w, b1.x, b1.y, b1.z, b1.w};
#pragma unroll
            for (int i = 0; i < 8; i++)
#pragma unroll
                for (int j = 0; j < 8; j++)
                    acc[i][j] += a[i] * b[j];
        }
        if (kt < 15) { STORES(buf ^ 1); __syncthreads(); buf ^= 1; }
    }
    float bv[8];
#pragma unroll
    for (int j = 0; j < 8; j++) bv[j] = bias ? bias[n0 + tx * 8 + j] : 0.f;
#pragma unroll
    for (int i = 0; i < 8; i++) {
        int mm = m0 + ty * 8 + i;
        if (mm >= M) continue;
        float* Cp = C + (size_t)mm * HDIM + n0 + tx * 8;
        *(float4*)Cp = make_float4(acc[i][0] + bv[0], acc[i][1] + bv[1],
                                   acc[i][2] + bv[2], acc[i][3] + bv[3]);
        *(float4*)(Cp + 4) = make_float4(acc[i][4] + bv[4], acc[i][5] + bv[5],
                                         acc[i][6] + bv[6], acc[i][7] + bv[7]);
    }
#undef LOADG
#undef STORES
}

// ---------------- launcher ---------------------------------------------------
extern "C" void kernel_launch(void* const* d_in, const int* in_sizes, int n_in,
                              void* d_out, int out_size) {
    const float* atomic_num = (const float*)d_in[0];
    const float* coord      = (const float*)d_in[1];
    const float* radius     = (const float*)d_in[2];
    const int*   src        = (const int*)  d_in[3];
    const int*   dst        = (const int*)  d_in[4];
    const int*   abs_mask   = (const int*)  d_in[5];
    const int*   graph_id   = (const int*)  d_in[6];
    const float* W_atom     = (const float*)d_in[7];
    const float* b_atom     = (const float*)d_in[8];
    const float* W_coord    = (const float*)d_in[9];
    const float* b_coord    = (const float*)d_in[10];
    const float* W_node     = (const float*)d_in[11];
    const float* b_node     = (const float*)d_in[12];
    const float* W_edge     = (const float*)d_in[13];
    const float* b_edge     = (const float*)d_in[14];
    const float* W_agg      = (const float*)d_in[15];
    const float* b_agg      = (const float*)d_in[16];
    const float* W_glu_a    = (const float*)d_in[17];
    const float* b_glu_a    = (const float*)d_in[18];
    const float* W_glu_b    = (const float*)d_in[19];
    const float* b_glu_b    = (const float*)d_in[20];
    const float* exp_l      = (const float*)d_in[21];
    const float* eps_l      = (const float*)d_in[22];
    const float* W_mlp      = (const float*)d_in[23];
    const float* b_mlp      = (const float*)d_in[24];
    float* out = (float*)d_out;

    int N = in_sizes[5];
    int E = in_sizes[2];

    float *p_h, *p_hs, *p_hd, *p_F1;
    __nv_bfloat16 *p_xh, *p_xl, *p_hh, *p_hl, *p_rh, *p_rl, *p_Bh, *p_Bl, *p_Fh, *p_Fl;
    cudaGetSymbolAddress((void**)&p_h,   g_h);
    cudaGetSymbolAddress((void**)&p_hs,  g_hs);
    cudaGetSymbolAddress((void**)&p_hd,  g_hd);
    cudaGetSymbolAddress((void**)&p_F1,  g_F1);
    cudaGetSymbolAddress((void**)&p_xh,  g_xa_hi);
    cudaGetSymbolAddress((void**)&p_xl,  g_xa_lo);
    cudaGetSymbolAddress((void**)&p_hh,  g_h_hi);
    cudaGetSymbolAddress((void**)&p_hl,  g_h_lo);
    cudaGetSymbolAddress((void**)&p_rh,  g_r_hi);
    cudaGetSymbolAddress((void**)&p_rl,  g_r_lo);
    cudaGetSymbolAddress((void**)&p_Bh,  g_Bt_hi);
    cudaGetSymbolAddress((void**)&p_Bl,  g_Bt_lo);
    cudaGetSymbolAddress((void**)&p_Fh,  g_F1t_hi);
    cudaGetSymbolAddress((void**)&p_Fl,  g_F1t_lo);

    const int MMA_SMEM = 81920;
    cudaFuncSetAttribute(mma_gemm, cudaFuncAttributeMaxDynamicSharedMemorySize, MMA_SMEM);

    int mtiles = (N + 127) / 128;
    int eb = (E + 255) / 256;
    int nhb = (N * HDIM + 255) / 256;
    int aggb = (N + 7) / 8;

    // CSR build
    zero_pre_kernel<<<80, 256>>>(N);
    hist_kernel<<<eb, 256>>>(dst, E);
    scan_kernel<<<1, 1024>>>(N);
    fill_kernel<<<eb, 256>>>(dst, E);

    // folds + conversions
    sgemm_pair<<<dim3(1, 2, 1), 256>>>(W_atom, ATOMD, W_node, W_node, p_F1, p_F1,
                                       nullptr, nullptr);          // F1 = W_atom @ Wn_top
    fold_small_kernel<<<1, HDIM>>>(W_coord, W_node, b_atom, b_coord, b_node);
    coord_init_kernel<<<nhb, 256>>>(coord, N);                     // addend into g_hd
    conv_x_kernel<<<(N * 128 + 255) / 256, 256>>>(atomic_num, N);
    conv_F1t_kernel<<<(HDIM * 128 + 255) / 256, 256>>>();
    conv_wT_kernel<<<dim3(HH / 256, 8, 1), 256>>>(W_agg, W_glu_a, W_glu_b);

    // init: h = x@F1 + coordpart (+fused bf16 split of h)
    mma_gemm<<<dim3(mtiles, 2, 1), 256, MMA_SMEM>>>(
        p_xh, p_xl, N, 128, p_Fh, p_Fl, p_Fh, p_Fl,
        p_h, p_h, nullptr, nullptr, p_hd, p_hh, p_hl);

    for (int l = 0; l < 2; l++) {
        const float* Wl = W_agg + (size_t)l * 3 * HH;
        uv_kernel<<<1, HDIM>>>(Wl + HH, W_edge, b_edge, b_agg + l * HDIM);
        // hs = h@Ws (z=0), hd = h@Wd (z=1)
        mma_gemm<<<dim3(mtiles, 2, 2), 256, MMA_SMEM>>>(
            p_hh, p_hl, N, HDIM,
            p_Bh + (size_t)(2 * l) * HH,     p_Bl + (size_t)(2 * l) * HH,
            p_Bh + (size_t)(2 * l + 1) * HH, p_Bl + (size_t)(2 * l + 1) * HH,
            p_hs, p_hd, nullptr, nullptr, nullptr, nullptr, nullptr);
        agg_kernel<<<aggb, 256>>>(src, radius, exp_l, eps_l, l, N);
        // ga = rst@Wa + ba (z=0), gb = rst@Wb + bb (z=1)
        mma_gemm<<<dim3(mtiles, 2, 2), 256, MMA_SMEM>>>(
            p_rh, p_rl, N, HDIM,
            p_Bh + (size_t)(4 + 2 * l) * HH, p_Bl + (size_t)(4 + 2 * l) * HH,
            p_Bh + (size_t)(5 + 2 * l) * HH, p_Bl + (size_t)(5 + 2 * l) * HH,
            p_hs, p_hd, b_glu_a + l * HDIM, b_glu_b + l * HDIM, nullptr, nullptr, nullptr);
        glu_kernel<<<nhb, 256>>>(N);
    }

    segsum_kernel<<<(N + 127) / 128, HDIM>>>(abs_mask, graph_id, N);
    mlp_kernel<<<GN, 128>>>(W_mlp, b_mlp, out, 1.0f / (float)N);
}

// round 7
// speedup vs baseline: 2.9470x; 1.0741x over previous
#include <cuda_runtime.h>
#include <cuda_bf16.h>
#include <stdint.h>
#include <cstdint>
#include <math.h>

#define N_NODES 20000
#define N_EDGES 640000
#define HDIM    256
#define GN      16
#define OUTD    100
#define ATOMD   118
#define HH      (HDIM * HDIM)

// ---------------- scratch ----------------------------------------------------
__device__ __align__(16) float g_h  [N_NODES * HDIM];
__device__ __align__(16) float g_hs [N_NODES * HDIM];
__device__ __align__(16) float g_hd [N_NODES * HDIM];
__device__ __align__(16) float g_uv [2 * 2 * HDIM];   // [layer][u|vp]
__device__ __align__(16) float g_F1 [ATOMD * HDIM];
__device__ __align__(16) float g_F2 [3 * HDIM];
__device__ __align__(16) float g_bf [HDIM];
__device__ __align__(16) float g_feat[GN * HDIM];
__device__ int   g_cnt [N_NODES + 1];
__device__ int   g_offs[N_NODES + 1];
__device__ int   g_wp  [N_NODES];
__device__ int   g_csr [N_EDGES];
// bf16 split operands
__device__ __align__(16) __nv_bfloat16 g_xa_hi[N_NODES * 128];
__device__ __align__(16) __nv_bfloat16 g_xa_lo[N_NODES * 128];
__device__ __align__(16) __nv_bfloat16 g_h_hi [N_NODES * HDIM];
__device__ __align__(16) __nv_bfloat16 g_h_lo [N_NODES * HDIM];
__device__ __align__(16) __nv_bfloat16 g_r_hi [N_NODES * HDIM];
__device__ __align__(16) __nv_bfloat16 g_r_lo [N_NODES * HDIM];
__device__ __align__(16) __nv_bfloat16 g_Bt_hi[8 * HH];
__device__ __align__(16) __nv_bfloat16 g_Bt_lo[8 * HH];
__device__ __align__(16) __nv_bfloat16 g_F1t_hi[HDIM * 128];
__device__ __align__(16) __nv_bfloat16 g_F1t_lo[HDIM * 128];

// ---------------- PTX helpers (all sm_80-legal) ------------------------------
__device__ __forceinline__ uint32_t smem_to_u32(const void* p) {
    uint32_t a;
    asm("{ .reg .u64 t; cvta.to.shared.u64 t, %1; cvt.u32.u64 %0, t; }" : "=r"(a) : "l"(p));
    return a;
}
__device__ __forceinline__ void ldsm4(uint32_t* r, uint32_t addr) {
    asm volatile("ldmatrix.sync.aligned.m8n8.x4.shared.b16 {%0,%1,%2,%3}, [%4];"
                 : "=r"(r[0]), "=r"(r[1]), "=r"(r[2]), "=r"(r[3]) : "r"(addr));
}
__device__ __forceinline__ void mma16816(float* c, const uint32_t* a, uint32_t b0, uint32_t b1) {
    asm volatile("mma.sync.aligned.m16n8k16.row.col.f32.bf16.bf16.f32 "
                 "{%0,%1,%2,%3}, {%4,%5,%6,%7}, {%8,%9}, {%0,%1,%2,%3};"
                 : "+f"(c[0]), "+f"(c[1]), "+f"(c[2]), "+f"(c[3])
                 : "r"(a[0]), "r"(a[1]), "r"(a[2]), "r"(a[3]), "r"(b0), "r"(b1));
}
__device__ __forceinline__ void cp_async16(uint32_t d, const void* s, int src_sz) {
    asm volatile("cp.async.cg.shared.global [%0], [%1], 16, %2;"
                 :: "r"(d), "l"(s), "r"(src_sz) : "memory");
}
#define CP_COMMIT() asm volatile("cp.async.commit_group;" ::: "memory")
#define CP_WAIT0()  asm volatile("cp.async.wait_group 0;" ::: "memory")

// ---------------- CSR build --------------------------------------------------
__global__ void zero_pre_kernel(int N) {
    int stride = gridDim.x * blockDim.x;
    int i = blockIdx.x * blockDim.x + threadIdx.x;
    for (int t = i; t < N + 1; t += stride) g_cnt[t] = 0;
    for (int t = i; t < GN * HDIM; t += stride) g_feat[t] = 0.f;
}
__global__ void hist_kernel(const int* __restrict__ dst, int E) {
    int e = blockIdx.x * blockDim.x + threadIdx.x;
    if (e < E) atomicAdd(&g_cnt[dst[e]], 1);
}
__global__ void scan_kernel(int N) {
    __shared__ int partial[1024];
    int t = threadIdx.x;
    int per = (N + 1023) / 1024;
    int start = t * per;
    int stop  = min(start + per, N);
    int sum = 0;
    for (int i = start; i < stop; i++) sum += g_cnt[i];
    partial[t] = sum;
    __syncthreads();
    for (int d = 1; d < 1024; d <<= 1) {
        int v = (t >= d) ? partial[t - d] : 0;
        __syncthreads();
        partial[t] += v;
        __syncthreads();
    }
    int run = (t == 0) ? 0 : partial[t - 1];
    for (int i = start; i < stop; i++) {
        g_offs[i] = run;
        g_wp[i]   = run;
        run += g_cnt[i];
    }
    if (t == 1023) g_offs[N] = partial[1023];
}
__global__ void fill_kernel(const int* __restrict__ dst, int E) {
    int e = blockIdx.x * blockDim.x + threadIdx.x;
    if (e < E) {
        int pos = atomicAdd(&g_wp[dst[e]], 1);
        g_csr[pos] = e;
    }
}

// ---------------- weight folding / conversions -------------------------------
__global__ void fold_small_kernel(const float* __restrict__ Wc,
                                  const float* __restrict__ Wn,
                                  const float* __restrict__ ba,
                                  const float* __restrict__ bc,
                                  const float* __restrict__ bn) {
    int j = threadIdx.x;
    float f0 = 0.f, f1 = 0.f, f2 = 0.f, bias = 0.f;
    for (int h = 0; h < HDIM; h++) {
        float wtop = Wn[h * HDIM + j];
        float wbot = Wn[(HDIM + h) * HDIM + j];
        f0 += Wc[0 * HDIM + h] * wbot;
        f1 += Wc[1 * HDIM + h] * wbot;
        f2 += Wc[2 * HDIM + h] * wbot;
        bias += ba[h] * wtop + bc[h] * wbot;
    }
    g_F2[0 * HDIM + j] = f0;
    g_F2[1 * HDIM + j] = f1;
    g_F2[2 * HDIM + j] = f2;
    g_bf[j] = bias + bn[j];
}

__global__ void coord_init_kernel(const float* __restrict__ coord, int N) {
    int idx = blockIdx.x * blockDim.x + threadIdx.x;
    if (idx >= N * HDIM) return;
    int n = idx >> 8;
    int j = idx & 255;
    float c0 = coord[n * 3], c1 = coord[n * 3 + 1], c2 = coord[n * 3 + 2];
    g_hd[idx] = c0 * g_F2[j] + c1 * g_F2[HDIM + j] + c2 * g_F2[2 * HDIM + j] + g_bf[j];
}

__device__ __forceinline__ void split_bf16(float v, __nv_bfloat16& hi, __nv_bfloat16& lo) {
    hi = __float2bfloat16(v);
    lo = __float2bfloat16(v - __bfloat162float(hi));
}

__global__ void conv_x_kernel(const float* __restrict__ x, int N) {
    int e = blockIdx.x * blockDim.x + threadIdx.x;
    if (e >= N * 128) return;
    int n = e >> 7, kk = e & 127;
    float v = (kk < ATOMD) ? x[n * ATOMD + kk] : 0.f;
    __nv_bfloat16 hi, lo;
    split_bf16(v, hi, lo);
    g_xa_hi[e] = hi;
    g_xa_lo[e] = lo;
}

__global__ void conv_wT_kernel(const float* __restrict__ W_agg,
                               const float* __restrict__ W_glu_a,
                               const float* __restrict__ W_glu_b) {
    int z = blockIdx.y;
    const float* src;
    switch (z) {
        case 0: src = W_agg; break;
        case 1: src = W_agg + 2 * HH; break;
        case 2: src = W_agg + 3 * HH; break;
        case 3: src = W_agg + 5 * HH; break;
        case 4: src = W_glu_a; break;
        case 5: src = W_glu_b; break;
        case 6: src = W_glu_a + HH; break;
        default: src = W_glu_b + HH; break;
    }
    int e = blockIdx.x * blockDim.x + threadIdx.x;
    int n = e >> 8, k = e & 255;
    float v = src[k * HDIM + n];
    __nv_bfloat16 hi, lo;
    split_bf16(v, hi, lo);
    g_Bt_hi[z * HH + e] = hi;
    g_Bt_lo[z * HH + e] = lo;
}

__global__ void conv_F1t_kernel() {
    int e = blockIdx.x * blockDim.x + threadIdx.x;
    if (e >= HDIM * 128) return;
    int n = e >> 7, k = e & 127;
    float v = (k < ATOMD) ? g_F1[k * HDIM + n] : 0.f;
    __nv_bfloat16 hi, lo;
    split_bf16(v, hi, lo);
    g_F1t_hi[e] = hi;
    g_F1t_lo[e] = lo;
}

// both layers' u/vp in one launch: block.y = layer
__global__ void uv_kernel(const float* __restrict__ W_agg,
                          const float* __restrict__ Wedge,
                          const float* __restrict__ bedge,
                          const float* __restrict__ b_agg) {
    int l = blockIdx.x;
    int j = threadIdx.x;
    const float* We = W_agg + (size_t)l * 3 * HH + HH;
    float u = 0.f, v = 0.f;
    for (int k = 0; k < HDIM; k++) {
        float we = We[k * HDIM + j];
        u += Wedge[k] * we;
        v += bedge[k] * we;
    }
    g_uv[l * 2 * HDIM + j] = u;
    g_uv[l * 2 * HDIM + HDIM + j] = v + b_agg[l * HDIM + j];
}

// ---------------- warp-per-node aggregation ---------------------------------
__global__ void agg_kernel(const int* __restrict__ src,
                           const float* __restrict__ radius,
                           const float* __restrict__ exp_l,
                           const float* __restrict__ eps_l, int l, int N) {
    int warp = (blockIdx.x * blockDim.x + threadIdx.x) >> 5;
    int lane = threadIdx.x & 31;
    if (warp >= N) return;
    float el = __ldg(&exp_l[l]);
    const float* uvb = g_uv + l * 2 * HDIM;
    int beg = g_offs[warp], end = g_offs[warp + 1];
    float4 acc0 = make_float4(0.f, 0.f, 0.f, 0.f);
    float4 acc1 = make_float4(0.f, 0.f, 0.f, 0.f);
    float s1 = 0.f, swr = 0.f;
    for (int base = beg; base < end; base += 32) {
        int p = base + lane;
        int s = 0;
        float w = 0.f;
        if (p < end) {
            int e = g_csr[p];
            s = src[e];
            float r = radius[e];
            w = __expf(__logf(r) * el);
            s1 += w;
            swr += w * r;
        }
        int cnt = min(32, end - base);
        for (int q = 0; q < cnt; q++) {
            int   sq = __shfl_sync(0xffffffffu, s, q);
            float wq = __shfl_sync(0xffffffffu, w, q);
            const float4* row = (const float4*)(g_hs + (size_t)sq * HDIM);
            float4 v0 = row[lane * 2];
            float4 v1 = row[lane * 2 + 1];
            acc0.x += wq * v0.x; acc0.y += wq * v0.y;
            acc0.z += wq * v0.z; acc0.w += wq * v0.w;
            acc1.x += wq * v1.x; acc1.y += wq * v1.y;
            acc1.z += wq * v1.z; acc1.w += wq * v1.w;
        }
    }
#pragma unroll
    for (int off = 16; off; off >>= 1) {
        s1  += __shfl_xor_sync(0xffffffffu, s1, off);
        swr += __shfl_xor_sync(0xffffffffu, swr, off);
    }
    float ep = 1.f + __ldg(&eps_l[l]);
    int j0 = lane * 8;
    float4 u0  = *(const float4*)(uvb + j0);
    float4 u1  = *(const float4*)(uvb + j0 + 4);
    float4 vp0 = *(const float4*)(uvb + HDIM + j0);
    float4 vp1 = *(const float4*)(uvb + HDIM + j0 + 4);
    size_t idx = (size_t)warp * HDIM + j0;
    float4 h0  = *(const float4*)(g_h + idx);
    float4 h1  = *(const float4*)(g_h + idx + 4);
    float4 d0  = *(const float4*)(g_hd + idx);
    float4 d1  = *(const float4*)(g_hd + idx + 4);
    float v[8];
    v[0] = ep * h0.x + acc0.x + s1 * (d0.x + vp0.x) + swr * u0.x;
    v[1] = ep * h0.y + acc0.y + s1 * (d0.y + vp0.y) + swr * u0.y;
    v[2] = ep * h0.z + acc0.z + s1 * (d0.z + vp0.z) + swr * u0.z;
    v[3] = ep * h0.w + acc0.w + s1 * (d0.w + vp0.w) + swr * u0.w;
    v[4] = ep * h1.x + acc1.x + s1 * (d1.x + vp1.x) + swr * u1.x;
    v[5] = ep * h1.y + acc1.y + s1 * (d1.y + vp1.y) + swr * u1.y;
    v[6] = ep * h1.z + acc1.z + s1 * (d1.z + vp1.z) + swr * u1.z;
    v[7] = ep * h1.w + acc1.w + s1 * (d1.w + vp1.w) + swr * u1.w;
    __nv_bfloat16 hi8[8];
    __nv_bfloat16 lo8[8];
#pragma unroll
    for (int j = 0; j < 8; j++) split_bf16(v[j], hi8[j], lo8[j]);
    *(uint4*)(g_r_hi + idx) = *(uint4*)hi8;
    *(uint4*)(g_r_lo + idx) = *(uint4*)lo8;
}

// h = ga * sigmoid(gb); also write bf16 split of h
__global__ void glu_kernel(int N) {
    int i = blockIdx.x * blockDim.x + threadIdx.x;
    if (i >= N * HDIM) return;
    float ga = g_hs[i], gb = g_hd[i];
    float h = ga * (1.f / (1.f + __expf(-gb)));
    g_h[i] = h;
    __nv_bfloat16 hi, lo;
    split_bf16(h, hi, lo);
    g_h_hi[i] = hi;
    g_h_lo[i] = lo;
}

__global__ void segsum_kernel(const int* __restrict__ mask,
                              const int* __restrict__ gid, int N) {
    int j  = threadIdx.x;
    int n0 = blockIdx.x * 128;
    if (n0 >= N) return;
    int n1 = min(n0 + 128, N);
    float acc = 0.f;
    int curg = gid[n0];
    for (int n = n0; n < n1; n++) {
        int g = gid[n];
        if (g != curg) {
            atomicAdd(&g_feat[curg * HDIM + j], acc);
            acc = 0.f;
            curg = g;
        }
        if (mask[n]) acc += g_h[n * HDIM + j];
    }
    atomicAdd(&g_feat[curg * HDIM + j], acc);
}

__global__ void mlp_kernel(const float* __restrict__ Wm,
                           const float* __restrict__ bm,
                           float* __restrict__ out, float invN) {
    int g = blockIdx.x;
    int o = threadIdx.x;
    if (o >= OUTD) return;
    float s = 0.f;
    for (int j = 0; j < HDIM; j++)
        s += g_feat[g * HDIM + j] * Wm[j * OUTD + o];
    s = s * invN + bm[o];
    out[g * OUTD + o] = 1.f / (1.f + __expf(-s));
}

// ---------------- mma.sync split-bf16 GEMM (cp.async pipeline) ---------------
// C[M,256] = (Ahi+Alo) @ Bt^T, 3-term bf16 split on HMMA tensor cores.
// Block: 128x128 tile (grid.y selects n-half), 256 thr = 8 warps of 32x64.
// SMEM: Ah/Al/Bh/Bl double-buffered [2][128][40] bf16 each = 81920 B.
#define TSB 10240            // one stage of one array, bytes (128*40*2)
#define OFF_AL 20480
#define OFF_BH 40960
#define OFF_BL 61440

__global__ __launch_bounds__(256, 2)
void mma_gemm(const __nv_bfloat16* __restrict__ Ahi, const __nv_bfloat16* __restrict__ Alo,
              int M, int Ktot,
              const __nv_bfloat16* __restrict__ Bh0, const __nv_bfloat16* __restrict__ Bl0,
              const __nv_bfloat16* __restrict__ Bh1, const __nv_bfloat16* __restrict__ Bl1,
              float* __restrict__ C0, float* __restrict__ C1,
              const float* __restrict__ bias0, const float* __restrict__ bias1,
              const float* __restrict__ addend,
              __nv_bfloat16* __restrict__ Chi, __nv_bfloat16* __restrict__ Clo) {
    extern __shared__ char smem[];
    const __nv_bfloat16* Bhi = blockIdx.z ? Bh1 : Bh0;
    const __nv_bfloat16* Blo = blockIdx.z ? Bl1 : Bl0;
    float* Cout = blockIdx.z ? C1 : C0;
    const float* bias = blockIdx.z ? bias1 : bias0;

    int tid = threadIdx.x;
    int wid = tid >> 5;
    int lane = tid & 31;
    int warp_m = wid & 3;
    int warp_n = wid >> 2;
    int m0 = blockIdx.x * 128;
    int n0 = blockIdx.y * 128;
    uint32_t sb = smem_to_u32(smem);

    float acc[2][8][4];
#pragma unroll
    for (int a = 0; a < 2; a++)
#pragma unroll
        for (int b = 0; b < 8; b++)
#pragma unroll
            for (int c = 0; c < 4; c++) acc[a][b][c] = 0.f;

    int KT = Ktot >> 5;

    int lrow = (lane & 7) + ((lane >> 3) & 1) * 8;
    int lcol = (lane >> 4) * 8;

    // per-thread load slots: 2 x (row, kc)
    int row0 = tid >> 2,           kc0 = (tid & 3) * 8;
    int row1 = (tid + 256) >> 2,   kc1 = (tid & 3) * 8;
    // clamped A row indices (cp.async src-size=0 for invalid rows)
    int arow0 = (m0 + row0 < M) ? (m0 + row0) : 0;
    int arow1 = (m0 + row1 < M) ? (m0 + row1) : 0;
    int asz0  = (m0 + row0 < M) ? 16 : 0;
    int asz1  = (m0 + row1 < M) ? 16 : 0;

#define LOAD_STAGE(kt, buf)                                                        \
    do {                                                                           \
        int k0 = (kt) * 32;                                                        \
        uint32_t d0 = sb + (buf) * TSB + ((uint32_t)row0 * 40 + kc0) * 2;          \
        uint32_t d1 = sb + (buf) * TSB + ((uint32_t)row1 * 40 + kc1) * 2;          \
        size_t ao0 = (size_t)arow0 * Ktot + k0 + kc0;                              \
        size_t ao1 = (size_t)arow1 * Ktot + k0 + kc1;                              \
        size_t bo0 = (size_t)(n0 + row0) * Ktot + k0 + kc0;                        \
        size_t bo1 = (size_t)(n0 + row1) * Ktot + k0 + kc1;                        \
        cp_async16(d0,          Ahi + ao0, asz0);                                  \
        cp_async16(d0 + OFF_AL, Alo + ao0, asz0);                                  \
        cp_async16(d0 + OFF_BH, Bhi + bo0, 16);                                    \
        cp_async16(d0 + OFF_BL, Blo + bo0, 16);                                    \
        cp_async16(d1,          Ahi + ao1, asz1);                                  \
        cp_async16(d1 + OFF_AL, Alo + ao1, asz1);                                  \
        cp_async16(d1 + OFF_BH, Bhi + bo1, 16);                                    \
        cp_async16(d1 + OFF_BL, Blo + bo1, 16);                                    \
    } while (0)

    LOAD_STAGE(0, 0);
    CP_COMMIT();

#pragma unroll 1
    for (int kt = 0; kt < KT; kt++) {
        int buf = kt & 1;
        CP_WAIT0();
        __syncthreads();
        if (kt + 1 < KT) {
            LOAD_STAGE(kt + 1, buf ^ 1);
            CP_COMMIT();
        }
#pragma unroll
        for (int ks = 0; ks < 2; ks++) {
            int kc = ks * 16 + lcol;
            uint32_t ah[2][4], al[2][4];
#pragma unroll
            for (int mt = 0; mt < 2; mt++) {
                int r = warp_m * 32 + mt * 16 + lrow;
                uint32_t addr = sb + buf * TSB + ((uint32_t)r * 40 + kc) * 2;
                ldsm4(ah[mt], addr);
                ldsm4(al[mt], addr + OFF_AL);
            }
#pragma unroll
            for (int ng = 0; ng < 4; ng++) {
                int r = warp_n * 64 + ng * 16 + lrow;
                uint32_t baddr = sb + buf * TSB + ((uint32_t)r * 40 + kc) * 2 + OFF_BH;
                uint32_t bh[4], bl[4];
                ldsm4(bh, baddr);
                ldsm4(bl, baddr + (OFF_BL - OFF_BH));
#pragma unroll
                for (int mt = 0; mt < 2; mt++) {
                    mma16816(acc[mt][2 * ng],     ah[mt], bh[0], bh[2]);
                    mma16816(acc[mt][2 * ng],     ah[mt], bl[0], bl[2]);
                    mma16816(acc[mt][2 * ng],     al[mt], bh[0], bh[2]);
                    mma16816(acc[mt][2 * ng + 1], ah[mt], bh[1], bh[3]);
                    mma16816(acc[mt][2 * ng + 1], ah[mt], bl[1], bl[3]);
                    mma16816(acc[mt][2 * ng + 1], al[mt], bh[1], bh[3]);
                }
            }
        }
    }

    // ---- epilogue ----
    int gi = lane >> 2;
    int ci = (lane & 3) * 2;
#pragma unroll
    for (int mt = 0; mt < 2; mt++) {
#pragma unroll
        for (int nt = 0; nt < 8; nt++) {
            float* a4 = acc[mt][nt];
            int col = n0 + warp_n * 64 + nt * 8 + ci;
            float b0 = 0.f, b1 = 0.f;
            if (bias) { b0 = __ldg(&bias[col]); b1 = __ldg(&bias[col + 1]); }
#pragma unroll
            for (int half = 0; half < 2; half++) {
                int row = m0 + warp_m * 32 + mt * 16 + gi + half * 8;
                if (row >= M) continue;
                float v0 = a4[half * 2]     + b0;
                float v1 = a4[half * 2 + 1] + b1;
                size_t o = (size_t)row * HDIM + col;
                if (addend) {
                    float2 t = *(const float2*)(addend + o);
                    v0 += t.x; v1 += t.y;
                }
                *(float2*)(Cout + o) = make_float2(v0, v1);
                if (Chi) {
                    __nv_bfloat16 h0, l0, h1, l1;
                    split_bf16(v0, h0, l0);
                    split_bf16(v1, h1, l1);
                    __nv_bfloat162 hv; hv.x = h0; hv.y = h1;
                    __nv_bfloat162 lv; lv.x = l0; lv.y = l1;
                    *(__nv_bfloat162*)(Chi + o) = hv;
                    *(__nv_bfloat162*)(Clo + o) = lv;
                }
            }
        }
    }
#undef LOAD_STAGE
}

// ---------------- small fp32 GEMM for the F1 fold (M=118) --------------------
__global__ __launch_bounds__(256, 2)
void sgemm_pair(const float* __restrict__ A, int M,
                const float* __restrict__ B0, const float* __restrict__ B1,
                float* __restrict__ C0, float* __restrict__ C1,
                const float* __restrict__ bias0, const float* __restrict__ bias1) {
    const float* B    = blockIdx.z ? B1 : B0;
    float*       C    = blockIdx.z ? C1 : C0;
    const float* bias = blockIdx.z ? bias1 : bias0;
    __shared__ float As[2][16][132];
    __shared__ float Bs[2][16][128];
    int tid = threadIdx.x;
    int m0 = blockIdx.x * 128;
    int n0 = blockIdx.y * 128;
    int tx = tid & 15, ty = tid >> 4;
    int ar = tid >> 2;
    int ac = (tid & 3) * 4;
    int bk = tid >> 5;
    int bn = (tid & 31) * 4;
    bool aval0 = (m0 + ar) < M;
    bool aval1 = (m0 + ar + 64) < M;
    const float* Arow0 = A + (size_t)(m0 + ar) * HDIM + ac;
    const float* Arow1 = A + (size_t)(m0 + ar + 64) * HDIM + ac;
    const float* Bp0 = B + (size_t)bk * HDIM + n0 + bn;
    const float* Bp1 = B + (size_t)(bk + 8) * HDIM + n0 + bn;
    float4 af0, af1, bf0, bf1;
    const float4 fz = make_float4(0.f, 0.f, 0.f, 0.f);
#define LOADG(k0) do { \
        af0 = aval0 ? *(const float4*)(Arow0 + (k0)) : fz; \
        af1 = aval1 ? *(const float4*)(Arow1 + (k0)) : fz; \
        bf0 = *(const float4*)(Bp0 + (size_t)(k0) * HDIM); \
        bf1 = *(const float4*)(Bp1 + (size_t)(k0) * HDIM); } while (0)
#define STORES(bufi) do { \
        As[bufi][ac + 0][ar] = af0.x; As[bufi][ac + 1][ar] = af0.y; \
        As[bufi][ac + 2][ar] = af0.z; As[bufi][ac + 3][ar] = af0.w; \
        As[bufi][ac + 0][ar + 64] = af1.x; As[bufi][ac + 1][ar + 64] = af1.y; \
        As[bufi][ac + 2][ar + 64] = af1.z; As[bufi][ac + 3][ar + 64] = af1.w; \
        *(float4*)&Bs[bufi][bk][bn] = bf0; *(float4*)&Bs[bufi][bk + 8][bn] = bf1; } while (0)
    float acc[8][8];
#pragma unroll
    for (int i = 0; i < 8; i++)
#pragma unroll
        for (int j = 0; j < 8; j++) acc[i][j] = 0.f;
    LOADG(0);
    STORES(0);
    __syncthreads();
    int buf = 0;
#pragma unroll 1
    for (int kt = 0; kt < 16; kt++) {
        if (kt < 15) LOADG((kt + 1) * 16);
#pragma unroll
        for (int k = 0; k < 16; k++) {
            float4 a0 = *(const float4*)&As[buf][k][ty * 8];
            float4 a1 = *(const float4*)&As[buf][k][ty * 8 + 4];
            float4 b0 = *(const float4*)&Bs[buf][k][tx * 8];
            float4 b1 = *(const float4*)&Bs[buf][k][tx * 8 + 4];
            float a[8] = {a0.x, a0.y, a0.z, a0.w, a1.x, a1.y, a1.z, a1.w};
            float b[8] = {b0.x, b0.y, b0.z, b0.w, b1.x, b1.y, b1.z, b1.w};
#pragma unroll
            for (int i = 0; i < 8; i++)
#pragma unroll
                for (int j = 0; j < 8; j++)
                    acc[i][j] += a[i] * b[j];
        }
        if (kt < 15) { STORES(buf ^ 1); __syncthreads(); buf ^= 1; }
    }
    float bv[8];
#pragma unroll
    for (int j = 0; j < 8; j++) bv[j] = bias ? bias[n0 + tx * 8 + j] : 0.f;
#pragma unroll
    for (int i = 0; i < 8; i++) {
        int mm = m0 + ty * 8 + i;
        if (mm >= M) continue;
        float* Cp = C + (size_t)mm * HDIM + n0 + tx * 8;
        *(float4*)Cp = make_float4(acc[i][0] + bv[0], acc[i][1] + bv[1],
                                   acc[i][2] + bv[2], acc[i][3] + bv[3]);
        *(float4*)(Cp + 4) = make_float4(acc[i][4] + bv[4], acc[i][5] + bv[5],
                                         acc[i][6] + bv[6], acc[i][7] + bv[7]);
    }
#undef LOADG
#undef STORES
}

// ---------------- launcher ---------------------------------------------------
extern "C" void kernel_launch(void* const* d_in, const int* in_sizes, int n_in,
                              void* d_out, int out_size) {
    const float* atomic_num = (const float*)d_in[0];
    const float* coord      = (const float*)d_in[1];
    const float* radius     = (const float*)d_in[2];
    const int*   src        = (const int*)  d_in[3];
    const int*   dst        = (const int*)  d_in[4];
    const int*   abs_mask   = (const int*)  d_in[5];
    const int*   graph_id   = (const int*)  d_in[6];
    const float* W_atom     = (const float*)d_in[7];
    const float* b_atom     = (const float*)d_in[8];
    const float* W_coord    = (const float*)d_in[9];
    const float* b_coord    = (const float*)d_in[10];
    const float* W_node     = (const float*)d_in[11];
    const float* b_node     = (const float*)d_in[12];
    const float* W_edge     = (const float*)d_in[13];
    const float* b_edge     = (const float*)d_in[14];
    const float* W_agg      = (const float*)d_in[15];
    const float* b_agg      = (const float*)d_in[16];
    const float* W_glu_a    = (const float*)d_in[17];
    const float* b_glu_a    = (const float*)d_in[18];
    const float* W_glu_b    = (const float*)d_in[19];
    const float* b_glu_b    = (const float*)d_in[20];
    const float* exp_l      = (const float*)d_in[21];
    const float* eps_l      = (const float*)d_in[22];
    const float* W_mlp      = (const float*)d_in[23];
    const float* b_mlp      = (const float*)d_in[24];
    float* out = (float*)d_out;

    int N = in_sizes[5];
    int E = in_sizes[2];

    float *p_h, *p_hs, *p_hd, *p_F1;
    __nv_bfloat16 *p_xh, *p_xl, *p_hh, *p_hl, *p_rh, *p_rl, *p_Bh, *p_Bl, *p_Fh, *p_Fl;
    cudaGetSymbolAddress((void**)&p_h,   g_h);
    cudaGetSymbolAddress((void**)&p_hs,  g_hs);
    cudaGetSymbolAddress((void**)&p_hd,  g_hd);
    cudaGetSymbolAddress((void**)&p_F1,  g_F1);
    cudaGetSymbolAddress((void**)&p_xh,  g_xa_hi);
    cudaGetSymbolAddress((void**)&p_xl,  g_xa_lo);
    cudaGetSymbolAddress((void**)&p_hh,  g_h_hi);
    cudaGetSymbolAddress((void**)&p_hl,  g_h_lo);
    cudaGetSymbolAddress((void**)&p_rh,  g_r_hi);
    cudaGetSymbolAddress((void**)&p_rl,  g_r_lo);
    cudaGetSymbolAddress((void**)&p_Bh,  g_Bt_hi);
    cudaGetSymbolAddress((void**)&p_Bl,  g_Bt_lo);
    cudaGetSymbolAddress((void**)&p_Fh,  g_F1t_hi);
    cudaGetSymbolAddress((void**)&p_Fl,  g_F1t_lo);

    const int MMA_SMEM = 81920;
    cudaFuncSetAttribute(mma_gemm, cudaFuncAttributeMaxDynamicSharedMemorySize, MMA_SMEM);

    int mtiles = (N + 127) / 128;
    int eb = (E + 255) / 256;
    int nhb = (N * HDIM + 255) / 256;
    int aggb = (N + 7) / 8;

    // CSR build
    zero_pre_kernel<<<80, 256>>>(N);
    hist_kernel<<<eb, 256>>>(dst, E);
    scan_kernel<<<1, 1024>>>(N);
    fill_kernel<<<eb, 256>>>(dst, E);

    // folds + conversions
    sgemm_pair<<<dim3(1, 2, 1), 256>>>(W_atom, ATOMD, W_node, W_node, p_F1, p_F1,
                                       nullptr, nullptr);          // F1 = W_atom @ Wn_top
    fold_small_kernel<<<1, HDIM>>>(W_coord, W_node, b_atom, b_coord, b_node);
    coord_init_kernel<<<nhb, 256>>>(coord, N);                     // addend into g_hd
    conv_x_kernel<<<(N * 128 + 255) / 256, 256>>>(atomic_num, N);
    conv_F1t_kernel<<<(HDIM * 128 + 255) / 256, 256>>>();
    conv_wT_kernel<<<dim3(HH / 256, 8, 1), 256>>>(W_agg, W_glu_a, W_glu_b);
    uv_kernel<<<2, HDIM>>>(W_agg, W_edge, b_edge, b_agg);

    // init: h = x@F1 + coordpart (+fused bf16 split of h)
    mma_gemm<<<dim3(mtiles, 2, 1), 256, MMA_SMEM>>>(
        p_xh, p_xl, N, 128, p_Fh, p_Fl, p_Fh, p_Fl,
        p_h, p_h, nullptr, nullptr, p_hd, p_hh, p_hl);

    for (int l = 0; l < 2; l++) {
        // hs = h@Ws (z=0), hd = h@Wd (z=1)
        mma_gemm<<<dim3(mtiles, 2, 2), 256, MMA_SMEM>>>(
            p_hh, p_hl, N, HDIM,
            p_Bh + (size_t)(2 * l) * HH,     p_Bl + (size_t)(2 * l) * HH,
            p_Bh + (size_t)(2 * l + 1) * HH, p_Bl + (size_t)(2 * l + 1) * HH,
            p_hs, p_hd, nullptr, nullptr, nullptr, nullptr, nullptr);
        agg_kernel<<<aggb, 256>>>(src, radius, exp_l, eps_l, l, N);
        // ga = rst@Wa + ba (z=0), gb = rst@Wb + bb (z=1)
        mma_gemm<<<dim3(mtiles, 2, 2), 256, MMA_SMEM>>>(
            p_rh, p_rl, N, HDIM,
            p_Bh + (size_t)(4 + 2 * l) * HH, p_Bl + (size_t)(4 + 2 * l) * HH,
            p_Bh + (size_t)(5 + 2 * l) * HH, p_Bl + (size_t)(5 + 2 * l) * HH,
            p_hs, p_hd, b_glu_a + l * HDIM, b_glu_b + l * HDIM, nullptr, nullptr, nullptr);
        glu_kernel<<<nhb, 256>>>(N);
    }

    segsum_kernel<<<(N + 127) / 128, HDIM>>>(abs_mask, graph_id, N);
    mlp_kernel<<<GN, 128>>>(W_mlp, b_mlp, out, 1.0f / (float)N);
}

// round 8
// speedup vs baseline: 3.1752x; 1.0774x over previous
#include <cuda_runtime.h>
#include <cuda_bf16.h>
#include <stdint.h>
#include <cstdint>
#include <math.h>

#define N_NODES 20000
#define N_EDGES 640000
#define HDIM    256
#define GN      16
#define OUTD    100
#define ATOMD   118
#define HH      (HDIM * HDIM)

// ---------------- scratch ----------------------------------------------------
__device__ __align__(16) float g_h  [N_NODES * HDIM];
__device__ __align__(16) float g_hs [N_NODES * HDIM];   // ga (GLU)
__device__ __align__(16) float g_hd [N_NODES * HDIM];   // hd / gb
__device__ __align__(16) float g_uv [2 * 2 * HDIM];     // [layer][u|vp]
__device__ __align__(16) float g_F1 [ATOMD * HDIM];
__device__ __align__(16) float g_F2 [3 * HDIM];
__device__ __align__(16) float g_bf [HDIM];
__device__ __align__(16) float g_feat[GN * HDIM];
__device__ int   g_cnt [N_NODES + 1];
__device__ int   g_offs[N_NODES + 1];
__device__ int   g_wp  [N_NODES];
__device__ int   g_csr [N_EDGES];
// bf16 split operands
__device__ __align__(16) __nv_bfloat16 g_xa_hi[N_NODES * 128];
__device__ __align__(16) __nv_bfloat16 g_xa_lo[N_NODES * 128];
__device__ __align__(16) __nv_bfloat16 g_h_hi [N_NODES * HDIM];
__device__ __align__(16) __nv_bfloat16 g_h_lo [N_NODES * HDIM];
__device__ __align__(16) __nv_bfloat16 g_r_hi [N_NODES * HDIM];
__device__ __align__(16) __nv_bfloat16 g_r_lo [N_NODES * HDIM];
__device__ __align__(16) __nv_bfloat16 g_s_hi [N_NODES * HDIM];  // hs in bf16 (gather src)
__device__ __align__(16) __nv_bfloat16 g_Bt_hi[8 * HH];
__device__ __align__(16) __nv_bfloat16 g_Bt_lo[8 * HH];
__device__ __align__(16) __nv_bfloat16 g_F1t_hi[HDIM * 128];
__device__ __align__(16) __nv_bfloat16 g_F1t_lo[HDIM * 128];

// ---------------- PTX helpers (all sm_80-legal) ------------------------------
__device__ __forceinline__ uint32_t smem_to_u32(const void* p) {
    uint32_t a;
    asm("{ .reg .u64 t; cvta.to.shared.u64 t, %1; cvt.u32.u64 %0, t; }" : "=r"(a) : "l"(p));
    return a;
}
__device__ __forceinline__ void ldsm4(uint32_t* r, uint32_t addr) {
    asm volatile("ldmatrix.sync.aligned.m8n8.x4.shared.b16 {%0,%1,%2,%3}, [%4];"
                 : "=r"(r[0]), "=r"(r[1]), "=r"(r[2]), "=r"(r[3]) : "r"(addr));
}
__device__ __forceinline__ void mma16816(float* c, const uint32_t* a, uint32_t b0, uint32_t b1) {
    asm volatile("mma.sync.aligned.m16n8k16.row.col.f32.bf16.bf16.f32 "
                 "{%0,%1,%2,%3}, {%4,%5,%6,%7}, {%8,%9}, {%0,%1,%2,%3};"
                 : "+f"(c[0]), "+f"(c[1]), "+f"(c[2]), "+f"(c[3])
                 : "r"(a[0]), "r"(a[1]), "r"(a[2]), "r"(a[3]), "r"(b0), "r"(b1));
}
__device__ __forceinline__ void cp_async16(uint32_t d, const void* s, int src_sz) {
    asm volatile("cp.async.cg.shared.global [%0], [%1], 16, %2;"
                 :: "r"(d), "l"(s), "r"(src_sz) : "memory");
}
#define CP_COMMIT() asm volatile("cp.async.commit_group;" ::: "memory")
#define CP_WAIT0()  asm volatile("cp.async.wait_group 0;" ::: "memory")

// ---------------- CSR build --------------------------------------------------
__global__ void zero_pre_kernel(int N) {
    int stride = gridDim.x * blockDim.x;
    int i = blockIdx.x * blockDim.x + threadIdx.x;
    for (int t = i; t < N + 1; t += stride) g_cnt[t] = 0;
    for (int t = i; t < GN * HDIM; t += stride) g_feat[t] = 0.f;
}
__global__ void hist_kernel(const int* __restrict__ dst, int E) {
    int e = blockIdx.x * blockDim.x + threadIdx.x;
    if (e < E) atomicAdd(&g_cnt[dst[e]], 1);
}
__global__ void scan_kernel(int N) {
    __shared__ int partial[1024];
    int t = threadIdx.x;
    int per = (N + 1023) / 1024;
    int start = t * per;
    int stop  = min(start + per, N);
    int sum = 0;
    for (int i = start; i < stop; i++) sum += g_cnt[i];
    partial[t] = sum;
    __syncthreads();
    for (int d = 1; d < 1024; d <<= 1) {
        int v = (t >= d) ? partial[t - d] : 0;
        __syncthreads();
        partial[t] += v;
        __syncthreads();
    }
    int run = (t == 0) ? 0 : partial[t - 1];
    for (int i = start; i < stop; i++) {
        g_offs[i] = run;
        g_wp[i]   = run;
        run += g_cnt[i];
    }
    if (t == 1023) g_offs[N] = partial[1023];
}
__global__ void fill_kernel(const int* __restrict__ dst, int E) {
    int e = blockIdx.x * blockDim.x + threadIdx.x;
    if (e < E) {
        int pos = atomicAdd(&g_wp[dst[e]], 1);
        g_csr[pos] = e;
    }
}

// ---------------- weight folding / conversions -------------------------------
__global__ void fold_small_kernel(const float* __restrict__ Wc,
                                  const float* __restrict__ Wn,
                                  const float* __restrict__ ba,
                                  const float* __restrict__ bc,
                                  const float* __restrict__ bn) {
    int j = threadIdx.x;
    float f0 = 0.f, f1 = 0.f, f2 = 0.f, bias = 0.f;
    for (int h = 0; h < HDIM; h++) {
        float wtop = Wn[h * HDIM + j];
        float wbot = Wn[(HDIM + h) * HDIM + j];
        f0 += Wc[0 * HDIM + h] * wbot;
        f1 += Wc[1 * HDIM + h] * wbot;
        f2 += Wc[2 * HDIM + h] * wbot;
        bias += ba[h] * wtop + bc[h] * wbot;
    }
    g_F2[0 * HDIM + j] = f0;
    g_F2[1 * HDIM + j] = f1;
    g_F2[2 * HDIM + j] = f2;
    g_bf[j] = bias + bn[j];
}

__global__ void coord_init_kernel(const float* __restrict__ coord, int N) {
    int idx = blockIdx.x * blockDim.x + threadIdx.x;
    if (idx >= N * HDIM) return;
    int n = idx >> 8;
    int j = idx & 255;
    float c0 = coord[n * 3], c1 = coord[n * 3 + 1], c2 = coord[n * 3 + 2];
    g_hd[idx] = c0 * g_F2[j] + c1 * g_F2[HDIM + j] + c2 * g_F2[2 * HDIM + j] + g_bf[j];
}

__device__ __forceinline__ void split_bf16(float v, __nv_bfloat16& hi, __nv_bfloat16& lo) {
    hi = __float2bfloat16(v);
    lo = __float2bfloat16(v - __bfloat162float(hi));
}

__global__ void conv_x_kernel(const float* __restrict__ x, int N) {
    int e = blockIdx.x * blockDim.x + threadIdx.x;
    if (e >= N * 128) return;
    int n = e >> 7, kk = e & 127;
    float v = (kk < ATOMD) ? x[n * ATOMD + kk] : 0.f;
    __nv_bfloat16 hi, lo;
    split_bf16(v, hi, lo);
    g_xa_hi[e] = hi;
    g_xa_lo[e] = lo;
}

__global__ void conv_wT_kernel(const float* __restrict__ W_agg,
                               const float* __restrict__ W_glu_a,
                               const float* __restrict__ W_glu_b) {
    int z = blockIdx.y;
    const float* src;
    switch (z) {
        case 0: src = W_agg; break;
        case 1: src = W_agg + 2 * HH; break;
        case 2: src = W_agg + 3 * HH; break;
        case 3: src = W_agg + 5 * HH; break;
        case 4: src = W_glu_a; break;
        case 5: src = W_glu_b; break;
        case 6: src = W_glu_a + HH; break;
        default: src = W_glu_b + HH; break;
    }
    int e = blockIdx.x * blockDim.x + threadIdx.x;
    int n = e >> 8, k = e & 255;
    float v = src[k * HDIM + n];
    __nv_bfloat16 hi, lo;
    split_bf16(v, hi, lo);
    g_Bt_hi[z * HH + e] = hi;
    g_Bt_lo[z * HH + e] = lo;
}

__global__ void conv_F1t_kernel() {
    int e = blockIdx.x * blockDim.x + threadIdx.x;
    if (e >= HDIM * 128) return;
    int n = e >> 7, k = e & 127;
    float v = (k < ATOMD) ? g_F1[k * HDIM + n] : 0.f;
    __nv_bfloat16 hi, lo;
    split_bf16(v, hi, lo);
    g_F1t_hi[e] = hi;
    g_F1t_lo[e] = lo;
}

__global__ void uv_kernel(const float* __restrict__ W_agg,
                          const float* __restrict__ Wedge,
                          const float* __restrict__ bedge,
                          const float* __restrict__ b_agg) {
    int l = blockIdx.x;
    int j = threadIdx.x;
    const float* We = W_agg + (size_t)l * 3 * HH + HH;
    float u = 0.f, v = 0.f;
    for (int k = 0; k < HDIM; k++) {
        float we = We[k * HDIM + j];
        u += Wedge[k] * we;
        v += bedge[k] * we;
    }
    g_uv[l * 2 * HDIM + j] = u;
    g_uv[l * 2 * HDIM + HDIM + j] = v + b_agg[l * HDIM + j];
}

// ---------------- warp-per-node aggregation (bf16 gather) --------------------
__global__ void agg_kernel(const int* __restrict__ src,
                           const float* __restrict__ radius,
                           const float* __restrict__ exp_l,
                           const float* __restrict__ eps_l, int l, int N) {
    int warp = (blockIdx.x * blockDim.x + threadIdx.x) >> 5;
    int lane = threadIdx.x & 31;
    if (warp >= N) return;
    float el = __ldg(&exp_l[l]);
    const float* uvb = g_uv + l * 2 * HDIM;
    int beg = g_offs[warp], end = g_offs[warp + 1];
    float4 acc0 = make_float4(0.f, 0.f, 0.f, 0.f);
    float4 acc1 = make_float4(0.f, 0.f, 0.f, 0.f);
    float s1 = 0.f, swr = 0.f;
    int j0 = lane * 8;
    for (int base = beg; base < end; base += 32) {
        int p = base + lane;
        int s = 0;
        float w = 0.f;
        if (p < end) {
            int e = g_csr[p];
            s = src[e];
            float r = radius[e];
            w = __expf(__logf(r) * el);
            s1 += w;
            swr += w * r;
        }
        int cnt = min(32, end - base);
        for (int q = 0; q < cnt; q++) {
            int   sq = __shfl_sync(0xffffffffu, s, q);
            float wq = __shfl_sync(0xffffffffu, w, q);
            uint4 pv = *(const uint4*)(g_s_hi + (size_t)sq * HDIM + j0);
            float2 f0 = __bfloat1622float2(*(__nv_bfloat162*)&pv.x);
            float2 f1 = __bfloat1622float2(*(__nv_bfloat162*)&pv.y);
            float2 f2 = __bfloat1622float2(*(__nv_bfloat162*)&pv.z);
            float2 f3 = __bfloat1622float2(*(__nv_bfloat162*)&pv.w);
            acc0.x += wq * f0.x; acc0.y += wq * f0.y;
            acc0.z += wq * f1.x; acc0.w += wq * f1.y;
            acc1.x += wq * f2.x; acc1.y += wq * f2.y;
            acc1.z += wq * f3.x; acc1.w += wq * f3.y;
        }
    }
#pragma unroll
    for (int off = 16; off; off >>= 1) {
        s1  += __shfl_xor_sync(0xffffffffu, s1, off);
        swr += __shfl_xor_sync(0xffffffffu, swr, off);
    }
    float ep = 1.f + __ldg(&eps_l[l]);
    float4 u0  = *(const float4*)(uvb + j0);
    float4 u1  = *(const float4*)(uvb + j0 + 4);
    float4 vp0 = *(const float4*)(uvb + HDIM + j0);
    float4 vp1 = *(const float4*)(uvb + HDIM + j0 + 4);
    size_t idx = (size_t)warp * HDIM + j0;
    float4 h0  = *(const float4*)(g_h + idx);
    float4 h1  = *(const float4*)(g_h + idx + 4);
    float4 d0  = *(const float4*)(g_hd + idx);
    float4 d1  = *(const float4*)(g_hd + idx + 4);
    float v[8];
    v[0] = ep * h0.x + acc0.x + s1 * (d0.x + vp0.x) + swr * u0.x;
    v[1] = ep * h0.y + acc0.y + s1 * (d0.y + vp0.y) + swr * u0.y;
    v[2] = ep * h0.z + acc0.z + s1 * (d0.z + vp0.z) + swr * u0.z;
    v[3] = ep * h0.w + acc0.w + s1 * (d0.w + vp0.w) + swr * u0.w;
    v[4] = ep * h1.x + acc1.x + s1 * (d1.x + vp1.x) + swr * u1.x;
    v[5] = ep * h1.y + acc1.y + s1 * (d1.y + vp1.y) + swr * u1.y;
    v[6] = ep * h1.z + acc1.z + s1 * (d1.z + vp1.z) + swr * u1.z;
    v[7] = ep * h1.w + acc1.w + s1 * (d1.w + vp1.w) + swr * u1.w;
    __nv_bfloat16 hi8[8];
    __nv_bfloat16 lo8[8];
#pragma unroll
    for (int j = 0; j < 8; j++) split_bf16(v[j], hi8[j], lo8[j]);
    *(uint4*)(g_r_hi + idx) = *(uint4*)hi8;
    *(uint4*)(g_r_lo + idx) = *(uint4*)lo8;
}

// h = ga * sigmoid(gb); also write bf16 split of h
__global__ void glu_kernel(int N) {
    int i = blockIdx.x * blockDim.x + threadIdx.x;
    if (i >= N * HDIM) return;
    float ga = g_hs[i], gb = g_hd[i];
    float h = ga * (1.f / (1.f + __expf(-gb)));
    g_h[i] = h;
    __nv_bfloat16 hi, lo;
    split_bf16(h, hi, lo);
    g_h_hi[i] = hi;
    g_h_lo[i] = lo;
}

__global__ void segsum_kernel(const int* __restrict__ mask,
                              const int* __restrict__ gid, int N) {
    int j  = threadIdx.x;
    int n0 = blockIdx.x * 128;
    if (n0 >= N) return;
    int n1 = min(n0 + 128, N);
    float acc = 0.f;
    int curg = gid[n0];
    for (int n = n0; n < n1; n++) {
        int g = gid[n];
        if (g != curg) {
            atomicAdd(&g_feat[curg * HDIM + j], acc);
            acc = 0.f;
            curg = g;
        }
        if (mask[n]) acc += g_h[n * HDIM + j];
    }
    atomicAdd(&g_feat[curg * HDIM + j], acc);
}

__global__ void mlp_kernel(const float* __restrict__ Wm,
                           const float* __restrict__ bm,
                           float* __restrict__ out, float invN) {
    int g = blockIdx.x;
    int o = threadIdx.x;
    if (o >= OUTD) return;
    float s = 0.f;
    for (int j = 0; j < HDIM; j++)
        s += g_feat[g * HDIM + j] * Wm[j * OUTD + o];
    s = s * invN + bm[o];
    out[g * OUTD + o] = 1.f / (1.f + __expf(-s));
}

// ---------------- mma.sync split-bf16 GEMM (cp.async pipeline) ---------------
#define TSB 10240
#define OFF_AL 20480
#define OFF_BH 40960
#define OFF_BL 61440

__global__ __launch_bounds__(256, 2)
void mma_gemm(const __nv_bfloat16* __restrict__ Ahi, const __nv_bfloat16* __restrict__ Alo,
              int M, int Ktot,
              const __nv_bfloat16* __restrict__ Bh0, const __nv_bfloat16* __restrict__ Bl0,
              const __nv_bfloat16* __restrict__ Bh1, const __nv_bfloat16* __restrict__ Bl1,
              float* __restrict__ C0, float* __restrict__ C1,
              const float* __restrict__ bias0, const float* __restrict__ bias1,
              const float* __restrict__ addend,
              __nv_bfloat16* __restrict__ Chi0, __nv_bfloat16* __restrict__ Clo0,
              __nv_bfloat16* __restrict__ Chi1, __nv_bfloat16* __restrict__ Clo1) {
    extern __shared__ char smem[];
    const __nv_bfloat16* Bhi = blockIdx.z ? Bh1 : Bh0;
    const __nv_bfloat16* Blo = blockIdx.z ? Bl1 : Bl0;
    float* Cout = blockIdx.z ? C1 : C0;
    const float* bias = blockIdx.z ? bias1 : bias0;
    __nv_bfloat16* Chi = blockIdx.z ? Chi1 : Chi0;
    __nv_bfloat16* Clo = blockIdx.z ? Clo1 : Clo0;

    int tid = threadIdx.x;
    int wid = tid >> 5;
    int lane = tid & 31;
    int warp_m = wid & 3;
    int warp_n = wid >> 2;
    int m0 = blockIdx.x * 128;
    int n0 = blockIdx.y * 128;
    uint32_t sb = smem_to_u32(smem);

    float acc[2][8][4];
#pragma unroll
    for (int a = 0; a < 2; a++)
#pragma unroll
        for (int b = 0; b < 8; b++)
#pragma unroll
            for (int c = 0; c < 4; c++) acc[a][b][c] = 0.f;

    int KT = Ktot >> 5;
    int lrow = (lane & 7) + ((lane >> 3) & 1) * 8;
    int lcol = (lane >> 4) * 8;

    int row0 = tid >> 2,           kc0 = (tid & 3) * 8;
    int row1 = (tid + 256) >> 2,   kc1 = (tid & 3) * 8;
    int arow0 = (m0 + row0 < M) ? (m0 + row0) : 0;
    int arow1 = (m0 + row1 < M) ? (m0 + row1) : 0;
    int asz0  = (m0 + row0 < M) ? 16 : 0;
    int asz1  = (m0 + row1 < M) ? 16 : 0;

#define LOAD_STAGE(kt, buf)                                                        \
    do {                                                                           \
        int k0 = (kt) * 32;                                                        \
        uint32_t d0 = sb + (buf) * TSB + ((uint32_t)row0 * 40 + kc0) * 2;          \
        uint32_t d1 = sb + (buf) * TSB + ((uint32_t)row1 * 40 + kc1) * 2;          \
        size_t ao0 = (size_t)arow0 * Ktot + k0 + kc0;                              \
        size_t ao1 = (size_t)arow1 * Ktot + k0 + kc1;                              \
        size_t bo0 = (size_t)(n0 + row0) * Ktot + k0 + kc0;                        \
        size_t bo1 = (size_t)(n0 + row1) * Ktot + k0 + kc1;                        \
        cp_async16(d0,          Ahi + ao0, asz0);                                  \
        cp_async16(d0 + OFF_AL, Alo + ao0, asz0);                                  \
        cp_async16(d0 + OFF_BH, Bhi + bo0, 16);                                    \
        cp_async16(d0 + OFF_BL, Blo + bo0, 16);                                    \
        cp_async16(d1,          Ahi + ao1, asz1);                                  \
        cp_async16(d1 + OFF_AL, Alo + ao1, asz1);                                  \
        cp_async16(d1 + OFF_BH, Bhi + bo1, 16);                                    \
        cp_async16(d1 + OFF_BL, Blo + bo1, 16);                                    \
    } while (0)

    LOAD_STAGE(0, 0);
    CP_COMMIT();

#pragma unroll 1
    for (int kt = 0; kt < KT; kt++) {
        int buf = kt & 1;
        CP_WAIT0();
        __syncthreads();
        if (kt + 1 < KT) {
            LOAD_STAGE(kt + 1, buf ^ 1);
            CP_COMMIT();
        }
#pragma unroll
        for (int ks = 0; ks < 2; ks++) {
            int kc = ks * 16 + lcol;
            uint32_t ah[2][4], al[2][4];
#pragma unroll
            for (int mt = 0; mt < 2; mt++) {
                int r = warp_m * 32 + mt * 16 + lrow;
                uint32_t addr = sb + buf * TSB + ((uint32_t)r * 40 + kc) * 2;
                ldsm4(ah[mt], addr);
                ldsm4(al[mt], addr + OFF_AL);
            }
#pragma unroll
            for (int ng = 0; ng < 4; ng++) {
                int r = warp_n * 64 + ng * 16 + lrow;
                uint32_t baddr = sb + buf * TSB + ((uint32_t)r * 40 + kc) * 2 + OFF_BH;
                uint32_t bh[4], bl[4];
                ldsm4(bh, baddr);
                ldsm4(bl, baddr + (OFF_BL - OFF_BH));
#pragma unroll
                for (int mt = 0; mt < 2; mt++) {
                    mma16816(acc[mt][2 * ng],     ah[mt], bh[0], bh[2]);
                    mma16816(acc[mt][2 * ng],     ah[mt], bl[0], bl[2]);
                    mma16816(acc[mt][2 * ng],     al[mt], bh[0], bh[2]);
                    mma16816(acc[mt][2 * ng + 1], ah[mt], bh[1], bh[3]);
                    mma16816(acc[mt][2 * ng + 1], ah[mt], bl[1], bl[3]);
                    mma16816(acc[mt][2 * ng + 1], al[mt], bh[1], bh[3]);
                }
            }
        }
    }

    // ---- epilogue (all outputs nullable) ----
    int gi = lane >> 2;
    int ci = (lane & 3) * 2;
#pragma unroll
    for (int mt = 0; mt < 2; mt++) {
#pragma unroll
        for (int nt = 0; nt < 8; nt++) {
            float* a4 = acc[mt][nt];
            int col = n0 + warp_n * 64 + nt * 8 + ci;
            float b0 = 0.f, b1 = 0.f;
            if (bias) { b0 = __ldg(&bias[col]); b1 = __ldg(&bias[col + 1]); }
#pragma unroll
            for (int half = 0; half < 2; half++) {
                int row = m0 + warp_m * 32 + mt * 16 + gi + half * 8;
                if (row >= M) continue;
                float v0 = a4[half * 2]     + b0;
                float v1 = a4[half * 2 + 1] + b1;
                size_t o = (size_t)row * HDIM + col;
                if (addend) {
                    float2 t = *(const float2*)(addend + o);
                    v0 += t.x; v1 += t.y;
                }
                if (Cout) *(float2*)(Cout + o) = make_float2(v0, v1);
                if (Chi) {
                    __nv_bfloat16 h0, l0, h1, l1;
                    split_bf16(v0, h0, l0);
                    split_bf16(v1, h1, l1);
                    __nv_bfloat162 hv; hv.x = h0; hv.y = h1;
                    *(__nv_bfloat162*)(Chi + o) = hv;
                    if (Clo) {
                        __nv_bfloat162 lv; lv.x = l0; lv.y = l1;
                        *(__nv_bfloat162*)(Clo + o) = lv;
                    }
                }
            }
        }
    }
#undef LOAD_STAGE
}

// ---------------- small fp32 GEMM for the F1 fold (M=118) --------------------
__global__ __launch_bounds__(256, 2)
void sgemm_pair(const float* __restrict__ A, int M,
                const float* __restrict__ B0, const float* __restrict__ B1,
                float* __restrict__ C0, float* __restrict__ C1,
                const float* __restrict__ bias0, const float* __restrict__ bias1) {
    const float* B    = blockIdx.z ? B1 : B0;
    float*       C    = blockIdx.z ? C1 : C0;
    const float* bias = blockIdx.z ? bias1 : bias0;
    __shared__ float As[2][16][132];
    __shared__ float Bs[2][16][128];
    int tid = threadIdx.x;
    int m0 = blockIdx.x * 128;
    int n0 = blockIdx.y * 128;
    int tx = tid & 15, ty = tid >> 4;
    int ar = tid >> 2;
    int ac = (tid & 3) * 4;
    int bk = tid >> 5;
    int bn = (tid & 31) * 4;
    bool aval0 = (m0 + ar) < M;
    bool aval1 = (m0 + ar + 64) < M;
    const float* Arow0 = A + (size_t)(m0 + ar) * HDIM + ac;
    const float* Arow1 = A + (size_t)(m0 + ar + 64) * HDIM + ac;
    const float* Bp0 = B + (size_t)bk * HDIM + n0 + bn;
    const float* Bp1 = B + (size_t)(bk + 8) * HDIM + n0 + bn;
    float4 af0, af1, bf0, bf1;
    const float4 fz = make_float4(0.f, 0.f, 0.f, 0.f);
#define LOADG(k0) do { \
        af0 = aval0 ? *(const float4*)(Arow0 + (k0)) : fz; \
        af1 = aval1 ? *(const float4*)(Arow1 + (k0)) : fz; \
        bf0 = *(const float4*)(Bp0 + (size_t)(k0) * HDIM); \
        bf1 = *(const float4*)(Bp1 + (size_t)(k0) * HDIM); } while (0)
#define STORES(bufi) do { \
        As[bufi][ac + 0][ar] = af0.x; As[bufi][ac + 1][ar] = af0.y; \
        As[bufi][ac + 2][ar] = af0.z; As[bufi][ac + 3][ar] = af0.w; \
        As[bufi][ac + 0][ar + 64] = af1.x; As[bufi][ac + 1][ar + 64] = af1.y; \
        As[bufi][ac + 2][ar + 64] = af1.z; As[bufi][ac + 3][ar + 64] = af1.w; \
        *(float4*)&Bs[bufi][bk][bn] = bf0; *(float4*)&Bs[bufi][bk + 8][bn] = bf1; } while (0)
    float acc[8][8];
#pragma unroll
    for (int i = 0; i < 8; i++)
#pragma unroll
        for (int j = 0; j < 8; j++) acc[i][j] = 0.f;
    LOADG(0);
    STORES(0);
    __syncthreads();
    int buf = 0;
#pragma unroll 1
    for (int kt = 0; kt < 16; kt++) {
        if (kt < 15) LOADG((kt + 1) * 16);
#pragma unroll
        for (int k = 0; k < 16; k++) {
            float4 a0 = *(const float4*)&As[buf][k][ty * 8];
            float4 a1 = *(const float4*)&As[buf][k][ty * 8 + 4];
            float4 b0 = *(const float4*)&Bs[buf][k][tx * 8];
            float4 b1 = *(const float4*)&Bs[buf][k][tx * 8 + 4];
            float a[8] = {a0.x, a0.y, a0.z, a0.w, a1.x, a1.y, a1.z, a1.w};
            float b[8] = {b0.x, b0.y, b0.z, b0.w, b1.x, b1.y, b1.z, b1.w};
#pragma unroll
            for (int i = 0; i < 8; i++)
#pragma unroll
                for (int j = 0; j < 8; j++)
                    acc[i][j] += a[i] * b[j];
        }
        if (kt < 15) { STORES(buf ^ 1); __syncthreads(); buf ^= 1; }
    }
    float bv[8];
#pragma unroll
    for (int j = 0; j < 8; j++) bv[j] = bias ? bias[n0 + tx * 8 + j] : 0.f;
#pragma unroll
    for (int i = 0; i < 8; i++) {
        int mm = m0 + ty * 8 + i;
        if (mm >= M) continue;
        float* Cp = C + (size_t)mm * HDIM + n0 + tx * 8;
        *(float4*)Cp = make_float4(acc[i][0] + bv[0], acc[i][1] + bv[1],
                                   acc[i][2] + bv[2], acc[i][3] + bv[3]);
        *(float4*)(Cp + 4) = make_float4(acc[i][4] + bv[4], acc[i][5] + bv[5],
                                         acc[i][6] + bv[6], acc[i][7] + bv[7]);
    }
#undef LOADG
#undef STORES
}

// ---------------- launcher ---------------------------------------------------
extern "C" void kernel_launch(void* const* d_in, const int* in_sizes, int n_in,
                              void* d_out, int out_size) {
    const float* atomic_num = (const float*)d_in[0];
    const float* coord      = (const float*)d_in[1];
    const float* radius     = (const float*)d_in[2];
    const int*   src        = (const int*)  d_in[3];
    const int*   dst        = (const int*)  d_in[4];
    const int*   abs_mask   = (const int*)  d_in[5];
    const int*   graph_id   = (const int*)  d_in[6];
    const float* W_atom     = (const float*)d_in[7];
    const float* b_atom     = (const float*)d_in[8];
    const float* W_coord    = (const float*)d_in[9];
    const float* b_coord    = (const float*)d_in[10];
    const float* W_node     = (const float*)d_in[11];
    const float* b_node     = (const float*)d_in[12];
    const float* W_edge     = (const float*)d_in[13];
    const float* b_edge     = (const float*)d_in[14];
    const float* W_agg      = (const float*)d_in[15];
    const float* b_agg      = (const float*)d_in[16];
    const float* W_glu_a    = (const float*)d_in[17];
    const float* b_glu_a    = (const float*)d_in[18];
    const float* W_glu_b    = (const float*)d_in[19];
    const float* b_glu_b    = (const float*)d_in[20];
    const float* exp_l      = (const float*)d_in[21];
    const float* eps_l      = (const float*)d_in[22];
    const float* W_mlp      = (const float*)d_in[23];
    const float* b_mlp      = (const float*)d_in[24];
    float* out = (float*)d_out;

    int N = in_sizes[5];
    int E = in_sizes[2];

    float *p_h, *p_hs, *p_hd, *p_F1;
    __nv_bfloat16 *p_xh, *p_xl, *p_hh, *p_hl, *p_rh, *p_rl, *p_sh, *p_Bh, *p_Bl, *p_Fh, *p_Fl;
    cudaGetSymbolAddress((void**)&p_h,   g_h);
    cudaGetSymbolAddress((void**)&p_hs,  g_hs);
    cudaGetSymbolAddress((void**)&p_hd,  g_hd);
    cudaGetSymbolAddress((void**)&p_F1,  g_F1);
    cudaGetSymbolAddress((void**)&p_xh,  g_xa_hi);
    cudaGetSymbolAddress((void**)&p_xl,  g_xa_lo);
    cudaGetSymbolAddress((void**)&p_hh,  g_h_hi);
    cudaGetSymbolAddress((void**)&p_hl,  g_h_lo);
    cudaGetSymbolAddress((void**)&p_rh,  g_r_hi);
    cudaGetSymbolAddress((void**)&p_rl,  g_r_lo);
    cudaGetSymbolAddress((void**)&p_sh,  g_s_hi);
    cudaGetSymbolAddress((void**)&p_Bh,  g_Bt_hi);
    cudaGetSymbolAddress((void**)&p_Bl,  g_Bt_lo);
    cudaGetSymbolAddress((void**)&p_Fh,  g_F1t_hi);
    cudaGetSymbolAddress((void**)&p_Fl,  g_F1t_lo);

    const int MMA_SMEM = 81920;
    cudaFuncSetAttribute(mma_gemm, cudaFuncAttributeMaxDynamicSharedMemorySize, MMA_SMEM);

    int mtiles = (N + 127) / 128;
    int eb = (E + 255) / 256;
    int nhb = (N * HDIM + 255) / 256;
    int aggb = (N + 7) / 8;

    // CSR build
    zero_pre_kernel<<<80, 256>>>(N);
    hist_kernel<<<eb, 256>>>(dst, E);
    scan_kernel<<<1, 1024>>>(N);
    fill_kernel<<<eb, 256>>>(dst, E);

    // folds + conversions
    sgemm_pair<<<dim3(1, 2, 1), 256>>>(W_atom, ATOMD, W_node, W_node, p_F1, p_F1,
                                       nullptr, nullptr);
    fold_small_kernel<<<1, HDIM>>>(W_coord, W_node, b_atom, b_coord, b_node);
    coord_init_kernel<<<nhb, 256>>>(coord, N);
    conv_x_kernel<<<(N * 128 + 255) / 256, 256>>>(atomic_num, N);
    conv_F1t_kernel<<<(HDIM * 128 + 255) / 256, 256>>>();
    conv_wT_kernel<<<dim3(HH / 256, 8, 1), 256>>>(W_agg, W_glu_a, W_glu_b);
    uv_kernel<<<2, HDIM>>>(W_agg, W_edge, b_edge, b_agg);

    // init: h = x@F1 + coordpart; write h fp32 + hi/lo
    mma_gemm<<<dim3(mtiles, 2, 1), 256, MMA_SMEM>>>(
        p_xh, p_xl, N, 128, p_Fh, p_Fl, p_Fh, p_Fl,
        p_h, p_h, nullptr, nullptr, p_hd,
        p_hh, p_hl, p_hh, p_hl);

    for (int l = 0; l < 2; l++) {
        // z=0: hs (bf16 hi only, for gather); z=1: hd (fp32 only)
        mma_gemm<<<dim3(mtiles, 2, 2), 256, MMA_SMEM>>>(
            p_hh, p_hl, N, HDIM,
            p_Bh + (size_t)(2 * l) * HH,     p_Bl + (size_t)(2 * l) * HH,
            p_Bh + (size_t)(2 * l + 1) * HH, p_Bl + (size_t)(2 * l + 1) * HH,
            nullptr, p_hd, nullptr, nullptr, nullptr,
            p_sh, nullptr, nullptr, nullptr);
        agg_kernel<<<aggb, 256>>>(src, radius, exp_l, eps_l, l, N);
        // z=0: ga (fp32); z=1: gb (fp32)
        mma_gemm<<<dim3(mtiles, 2, 2), 256, MMA_SMEM>>>(
            p_rh, p_rl, N, HDIM,
            p_Bh + (size_t)(4 + 2 * l) * HH, p_Bl + (size_t)(4 + 2 * l) * HH,
            p_Bh + (size_t)(5 + 2 * l) * HH, p_Bl + (size_t)(5 + 2 * l) * HH,
            p_hs, p_hd, b_glu_a + l * HDIM, b_glu_b + l * HDIM, nullptr,
            nullptr, nullptr, nullptr, nullptr);
        glu_kernel<<<nhb, 256>>>(N);
    }

    segsum_kernel<<<(N + 127) / 128, HDIM>>>(abs_mask, graph_id, N);
    mlp_kernel<<<GN, 128>>>(W_mlp, b_mlp, out, 1.0f / (float)N);
}

// round 10
// speedup vs baseline: 3.1756x; 1.0001x over previous
#include <cuda_runtime.h>
#include <cuda_bf16.h>
#include <stdint.h>
#include <cstdint>
#include <math.h>

#define N_NODES 20000
#define N_EDGES 640000
#define HDIM    256
#define GN      16
#define OUTD    100
#define ATOMD   118
#define HH      (HDIM * HDIM)

// ---------------- scratch ----------------------------------------------------
__device__ __align__(16) float g_h  [N_NODES * HDIM];
__device__ __align__(16) float g_hs [N_NODES * HDIM];   // ga (GLU)
__device__ __align__(16) float g_hd [N_NODES * HDIM];   // hd / gb
__device__ __align__(16) float g_uv [2 * 2 * HDIM];     // [layer][u|vp]
__device__ __align__(16) float g_F1 [ATOMD * HDIM];
__device__ __align__(16) float g_F2 [3 * HDIM];
__device__ __align__(16) float g_bf [HDIM];
__device__ __align__(16) float g_feat[GN * HDIM];
__device__ int   g_cnt [N_NODES + 1];
__device__ int   g_offs[N_NODES + 1];
__device__ int   g_wp  [N_NODES];
__device__ int   g_csr [N_EDGES];
// bf16 split operands
__device__ __align__(16) __nv_bfloat16 g_xa_hi[N_NODES * 128];
__device__ __align__(16) __nv_bfloat16 g_xa_lo[N_NODES * 128];
__device__ __align__(16) __nv_bfloat16 g_h_hi [N_NODES * HDIM];
__device__ __align__(16) __nv_bfloat16 g_h_lo [N_NODES * HDIM];
__device__ __align__(16) __nv_bfloat16 g_r_hi [N_NODES * HDIM];
__device__ __align__(16) __nv_bfloat16 g_r_lo [N_NODES * HDIM];
__device__ __align__(16) __nv_bfloat16 g_s_hi [N_NODES * HDIM];  // hs bf16 (gather src)
__device__ __align__(16) __nv_bfloat16 g_Bt_hi[8 * HH];
__device__ __align__(16) __nv_bfloat16 g_Bt_lo[8 * HH];
__device__ __align__(16) __nv_bfloat16 g_F1t_hi[HDIM * 128];
__device__ __align__(16) __nv_bfloat16 g_F1t_lo[HDIM * 128];

// ---------------- PTX helpers (all sm_80-legal) ------------------------------
__device__ __forceinline__ uint32_t smem_to_u32(const void* p) {
    uint32_t a;
    asm("{ .reg .u64 t; cvta.to.shared.u64 t, %1; cvt.u32.u64 %0, t; }" : "=r"(a) : "l"(p));
    return a;
}
__device__ __forceinline__ void ldsm4(uint32_t* r, uint32_t addr) {
    asm volatile("ldmatrix.sync.aligned.m8n8.x4.shared.b16 {%0,%1,%2,%3}, [%4];"
                 : "=r"(r[0]), "=r"(r[1]), "=r"(r[2]), "=r"(r[3]) : "r"(addr));
}
__device__ __forceinline__ void mma16816(float* c, const uint32_t* a, uint32_t b0, uint32_t b1) {
    asm volatile("mma.sync.aligned.m16n8k16.row.col.f32.bf16.bf16.f32 "
                 "{%0,%1,%2,%3}, {%4,%5,%6,%7}, {%8,%9}, {%0,%1,%2,%3};"
                 : "+f"(c[0]), "+f"(c[1]), "+f"(c[2]), "+f"(c[3])
                 : "r"(a[0]), "r"(a[1]), "r"(a[2]), "r"(a[3]), "r"(b0), "r"(b1));
}
__device__ __forceinline__ void cp_async16(uint32_t d, const void* s, int src_sz) {
    asm volatile("cp.async.cg.shared.global [%0], [%1], 16, %2;"
                 :: "r"(d), "l"(s), "r"(src_sz) : "memory");
}
#define CP_COMMIT() asm volatile("cp.async.commit_group;" ::: "memory")
#define CP_WAIT0()  asm volatile("cp.async.wait_group 0;" ::: "memory")

// ---------------- CSR build --------------------------------------------------
__global__ void zero_pre_kernel(int N) {
    int stride = gridDim.x * blockDim.x;
    int i = blockIdx.x * blockDim.x + threadIdx.x;
    for (int t = i; t < N + 1; t += stride) g_cnt[t] = 0;
    for (int t = i; t < GN * HDIM; t += stride) g_feat[t] = 0.f;
}
__global__ void hist_kernel(const int* __restrict__ dst, int E) {
    int e = blockIdx.x * blockDim.x + threadIdx.x;
    if (e < E) atomicAdd(&g_cnt[dst[e]], 1);
}
__global__ void scan_kernel(int N) {
    __shared__ int partial[1024];
    int t = threadIdx.x;
    int per = (N + 1023) / 1024;
    int start = t * per;
    int stop  = min(start + per, N);
    int sum = 0;
    for (int i = start; i < stop; i++) sum += g_cnt[i];
    partial[t] = sum;
    __syncthreads();
    for (int d = 1; d < 1024; d <<= 1) {
        int v = (t >= d) ? partial[t - d] : 0;
        __syncthreads();
        partial[t] += v;
        __syncthreads();
    }
    int run = (t == 0) ? 0 : partial[t - 1];
    for (int i = start; i < stop; i++) {
        g_offs[i] = run;
        g_wp[i]   = run;
        run += g_cnt[i];
    }
    if (t == 1023) g_offs[N] = partial[1023];
}
__global__ void fill_kernel(const int* __restrict__ dst, int E) {
    int e = blockIdx.x * blockDim.x + threadIdx.x;
    if (e < E) {
        int pos = atomicAdd(&g_wp[dst[e]], 1);
        g_csr[pos] = e;
    }
}

// ---------------- weight folding / conversions -------------------------------
__global__ void fold_small_kernel(const float* __restrict__ Wc,
                                  const float* __restrict__ Wn,
                                  const float* __restrict__ ba,
                                  const float* __restrict__ bc,
                                  const float* __restrict__ bn) {
    int j = threadIdx.x;
    float f0 = 0.f, f1 = 0.f, f2 = 0.f, bias = 0.f;
    for (int h = 0; h < HDIM; h++) {
        float wtop = Wn[h * HDIM + j];
        float wbot = Wn[(HDIM + h) * HDIM + j];
        f0 += Wc[0 * HDIM + h] * wbot;
        f1 += Wc[1 * HDIM + h] * wbot;
        f2 += Wc[2 * HDIM + h] * wbot;
        bias += ba[h] * wtop + bc[h] * wbot;
    }
    g_F2[0 * HDIM + j] = f0;
    g_F2[1 * HDIM + j] = f1;
    g_F2[2 * HDIM + j] = f2;
    g_bf[j] = bias + bn[j];
}

__global__ void coord_init_kernel(const float* __restrict__ coord, int N) {
    int idx = blockIdx.x * blockDim.x + threadIdx.x;
    if (idx >= N * HDIM) return;
    int n = idx >> 8;
    int j = idx & 255;
    float c0 = coord[n * 3], c1 = coord[n * 3 + 1], c2 = coord[n * 3 + 2];
    g_hd[idx] = c0 * g_F2[j] + c1 * g_F2[HDIM + j] + c2 * g_F2[2 * HDIM + j] + g_bf[j];
}

__device__ __forceinline__ void split_bf16(float v, __nv_bfloat16& hi, __nv_bfloat16& lo) {
    hi = __float2bfloat16(v);
    lo = __float2bfloat16(v - __bfloat162float(hi));
}

__global__ void conv_x_kernel(const float* __restrict__ x, int N) {
    int e = blockIdx.x * blockDim.x + threadIdx.x;
    if (e >= N * 128) return;
    int n = e >> 7, kk = e & 127;
    float v = (kk < ATOMD) ? x[n * ATOMD + kk] : 0.f;
    __nv_bfloat16 hi, lo;
    split_bf16(v, hi, lo);
    g_xa_hi[e] = hi;
    g_xa_lo[e] = lo;
}

__global__ void conv_wT_kernel(const float* __restrict__ W_agg,
                               const float* __restrict__ W_glu_a,
                               const float* __restrict__ W_glu_b) {
    int z = blockIdx.y;
    const float* src;
    switch (z) {
        case 0: src = W_agg; break;
        case 1: src = W_agg + 2 * HH; break;
        case 2: src = W_agg + 3 * HH; break;
        case 3: src = W_agg + 5 * HH; break;
        case 4: src = W_glu_a; break;
        case 5: src = W_glu_b; break;
        case 6: src = W_glu_a + HH; break;
        default: src = W_glu_b + HH; break;
    }
    int e = blockIdx.x * blockDim.x + threadIdx.x;
    int n = e >> 8, k = e & 255;
    float v = src[k * HDIM + n];
    __nv_bfloat16 hi, lo;
    split_bf16(v, hi, lo);
    g_Bt_hi[z * HH + e] = hi;
    g_Bt_lo[z * HH + e] = lo;
}

__global__ void conv_F1t_kernel() {
    int e = blockIdx.x * blockDim.x + threadIdx.x;
    if (e >= HDIM * 128) return;
    int n = e >> 7, k = e & 127;
    float v = (k < ATOMD) ? g_F1[k * HDIM + n] : 0.f;
    __nv_bfloat16 hi, lo;
    split_bf16(v, hi, lo);
    g_F1t_hi[e] = hi;
    g_F1t_lo[e] = lo;
}

__global__ void uv_kernel(const float* __restrict__ W_agg,
                          const float* __restrict__ Wedge,
                          const float* __restrict__ bedge,
                          const float* __restrict__ b_agg) {
    int l = blockIdx.x;
    int j = threadIdx.x;
    const float* We = W_agg + (size_t)l * 3 * HH + HH;
    float u = 0.f, v = 0.f;
    for (int k = 0; k < HDIM; k++) {
        float we = We[k * HDIM + j];
        u += Wedge[k] * we;
        v += bedge[k] * we;
    }
    g_uv[l * 2 * HDIM + j] = u;
    g_uv[l * 2 * HDIM + HDIM + j] = v + b_agg[l * HDIM + j];
}

// ---------------- warp-per-node aggregation (bf16 gather) --------------------
__global__ void agg_kernel(const int* __restrict__ src,
                           const float* __restrict__ radius,
                           const float* __restrict__ exp_l,
                           const float* __restrict__ eps_l, int l, int N) {
    int warp = (blockIdx.x * blockDim.x + threadIdx.x) >> 5;
    int lane = threadIdx.x & 31;
    if (warp >= N) return;
    float el = __ldg(&exp_l[l]);
    const float* uvb = g_uv + l * 2 * HDIM;
    int beg = g_offs[warp], end = g_offs[warp + 1];
    float4 acc0 = make_float4(0.f, 0.f, 0.f, 0.f);
    float4 acc1 = make_float4(0.f, 0.f, 0.f, 0.f);
    float s1 = 0.f, swr = 0.f;
    int j0 = lane * 8;
    for (int base = beg; base < end; base += 32) {
        int p = base + lane;
        int s = 0;
        float w = 0.f;
        if (p < end) {
            int e = g_csr[p];
            s = src[e];
            float r = radius[e];
            w = __expf(__logf(r) * el);
            s1 += w;
            swr += w * r;
        }
        int cnt = min(32, end - base);
        for (int q = 0; q < cnt; q++) {
            int   sq = __shfl_sync(0xffffffffu, s, q);
            float wq = __shfl_sync(0xffffffffu, w, q);
            uint4 pv = *(const uint4*)(g_s_hi + (size_t)sq * HDIM + j0);
            float2 f0 = __bfloat1622float2(*(__nv_bfloat162*)&pv.x);
            float2 f1 = __bfloat1622float2(*(__nv_bfloat162*)&pv.y);
            float2 f2 = __bfloat1622float2(*(__nv_bfloat162*)&pv.z);
            float2 f3 = __bfloat1622float2(*(__nv_bfloat162*)&pv.w);
            acc0.x += wq * f0.x; acc0.y += wq * f0.y;
            acc0.z += wq * f1.x; acc0.w += wq * f1.y;
            acc1.x += wq * f2.x; acc1.y += wq * f2.y;
            acc1.z += wq * f3.x; acc1.w += wq * f3.y;
        }
    }
#pragma unroll
    for (int off = 16; off; off >>= 1) {
        s1  += __shfl_xor_sync(0xffffffffu, s1, off);
        swr += __shfl_xor_sync(0xffffffffu, swr, off);
    }
    float ep = 1.f + __ldg(&eps_l[l]);
    float4 u0  = *(const float4*)(uvb + j0);
    float4 u1  = *(const float4*)(uvb + j0 + 4);
    float4 vp0 = *(const float4*)(uvb + HDIM + j0);
    float4 vp1 = *(const float4*)(uvb + HDIM + j0 + 4);
    size_t idx = (size_t)warp * HDIM + j0;
    float4 h0  = *(const float4*)(g_h + idx);
    float4 h1  = *(const float4*)(g_h + idx + 4);
    float4 d0  = *(const float4*)(g_hd + idx);
    float4 d1  = *(const float4*)(g_hd + idx + 4);
    float v[8];
    v[0] = ep * h0.x + acc0.x + s1 * (d0.x + vp0.x) + swr * u0.x;
    v[1] = ep * h0.y + acc0.y + s1 * (d0.y + vp0.y) + swr * u0.y;
    v[2] = ep * h0.z + acc0.z + s1 * (d0.z + vp0.z) + swr * u0.z;
    v[3] = ep * h0.w + acc0.w + s1 * (d0.w + vp0.w) + swr * u0.w;
    v[4] = ep * h1.x + acc1.x + s1 * (d1.x + vp1.x) + swr * u1.x;
    v[5] = ep * h1.y + acc1.y + s1 * (d1.y + vp1.y) + swr * u1.y;
    v[6] = ep * h1.z + acc1.z + s1 * (d1.z + vp1.z) + swr * u1.z;
    v[7] = ep * h1.w + acc1.w + s1 * (d1.w + vp1.w) + swr * u1.w;
    __nv_bfloat16 hi8[8];
    __nv_bfloat16 lo8[8];
#pragma unroll
    for (int j = 0; j < 8; j++) split_bf16(v[j], hi8[j], lo8[j]);
    *(uint4*)(g_r_hi + idx) = *(uint4*)hi8;
    *(uint4*)(g_r_lo + idx) = *(uint4*)lo8;
}

// h = ga * sigmoid(gb); also write fp32 h and bf16 split of h (layer 0 only)
__global__ void glu_kernel(int N) {
    int i = blockIdx.x * blockDim.x + threadIdx.x;
    if (i >= N * HDIM) return;
    float ga = g_hs[i], gb = g_hd[i];
    float h = ga * (1.f / (1.f + __expf(-gb)));
    g_h[i] = h;
    __nv_bfloat16 hi, lo;
    split_bf16(h, hi, lo);
    g_h_hi[i] = hi;
    g_h_lo[i] = lo;
}

// last layer: fused GLU + masked segment-sum (no materialization of h)
__global__ void glu_segsum_kernel(const int* __restrict__ mask,
                                  const int* __restrict__ gid, int N) {
    int j  = threadIdx.x;
    int n0 = blockIdx.x * 128;
    if (n0 >= N) return;
    int n1 = min(n0 + 128, N);
    float acc = 0.f;
    int curg = gid[n0];
    for (int n = n0; n < n1; n++) {
        int g = gid[n];
        if (g != curg) {
            atomicAdd(&g_feat[curg * HDIM + j], acc);
            acc = 0.f;
            curg = g;
        }
        if (mask[n]) {
            size_t o = (size_t)n * HDIM + j;
            float ga = g_hs[o], gb = g_hd[o];
            acc += ga * (1.f / (1.f + __expf(-gb)));
        }
    }
    atomicAdd(&g_feat[curg * HDIM + j], acc);
}

__global__ void mlp_kernel(const float* __restrict__ Wm,
                           const float* __restrict__ bm,
                           float* __restrict__ out, float invN) {
    int g = blockIdx.x;
    int o = threadIdx.x;
    if (o >= OUTD) return;
    float s = 0.f;
    for (int j = 0; j < HDIM; j++)
        s += g_feat[g * HDIM + j] * Wm[j * OUTD + o];
    s = s * invN + bm[o];
    out[g * OUTD + o] = 1.f / (1.f + __expf(-s));
}

// ---------------- mma.sync split-bf16 GEMM (512 thr, 32x32 warp tiles) -------
#define TSB 10240
#define OFF_AL 20480
#define OFF_BH 40960
#define OFF_BL 61440

__global__ __launch_bounds__(512, 2)
void mma_gemm(const __nv_bfloat16* __restrict__ Ahi, const __nv_bfloat16* __restrict__ Alo,
              int M, int Ktot,
              const __nv_bfloat16* __restrict__ Bh0, const __nv_bfloat16* __restrict__ Bl0,
              const __nv_bfloat16* __restrict__ Bh1, const __nv_bfloat16* __restrict__ Bl1,
              float* __restrict__ C0, float* __restrict__ C1,
              const float* __restrict__ bias0, const float* __restrict__ bias1,
              const float* __restrict__ addend,
              __nv_bfloat16* __restrict__ Chi0, __nv_bfloat16* __restrict__ Clo0,
              __nv_bfloat16* __restrict__ Chi1, __nv_bfloat16* __restrict__ Clo1) {
    extern __shared__ char smem[];
    const __nv_bfloat16* Bhi = blockIdx.z ? Bh1 : Bh0;
    const __nv_bfloat16* Blo = blockIdx.z ? Bl1 : Bl0;
    float* Cout = blockIdx.z ? C1 : C0;
    const float* bias = blockIdx.z ? bias1 : bias0;
    __nv_bfloat16* Chi = blockIdx.z ? Chi1 : Chi0;
    __nv_bfloat16* Clo = blockIdx.z ? Clo1 : Clo0;

    int tid = threadIdx.x;
    int wid = tid >> 5;
    int lane = tid & 31;
    int warp_m = wid & 3;       // 0..3 -> 32-row slice
    int warp_n = wid >> 2;      // 0..3 -> 32-col slice
    int m0 = blockIdx.x * 128;
    int n0 = blockIdx.y * 128;
    uint32_t sb = smem_to_u32(smem);

    float acc[2][4][4];
#pragma unroll
    for (int a = 0; a < 2; a++)
#pragma unroll
        for (int b = 0; b < 4; b++)
#pragma unroll
            for (int c = 0; c < 4; c++) acc[a][b][c] = 0.f;

    int KT = Ktot >> 5;
    int lrow = (lane & 7) + ((lane >> 3) & 1) * 8;
    int lcol = (lane >> 4) * 8;

    // one 16B slot per thread per array per stage: 512 threads cover 128x32
    int rowL = tid >> 2, kcL = (tid & 3) * 8;
    int arowL = (m0 + rowL < M) ? (m0 + rowL) : 0;
    int aszL  = (m0 + rowL < M) ? 16 : 0;

#define LOAD_STAGE(kt, buf)                                                        \
    do {                                                                           \
        int k0 = (kt) * 32;                                                        \
        uint32_t dL = sb + (buf) * TSB + ((uint32_t)rowL * 40 + kcL) * 2;          \
        size_t aoL = (size_t)arowL * Ktot + k0 + kcL;                              \
        size_t boL = (size_t)(n0 + rowL) * Ktot + k0 + kcL;                        \
        cp_async16(dL,          Ahi + aoL, aszL);                                  \
        cp_async16(dL + OFF_AL, Alo + aoL, aszL);                                  \
        cp_async16(dL + OFF_BH, Bhi + boL, 16);                                    \
        cp_async16(dL + OFF_BL, Blo + boL, 16);                                    \
    } while (0)

    LOAD_STAGE(0, 0);
    CP_COMMIT();

#pragma unroll 1
    for (int kt = 0; kt < KT; kt++) {
        int buf = kt & 1;
        CP_WAIT0();
        __syncthreads();
        if (kt + 1 < KT) {
            LOAD_STAGE(kt + 1, buf ^ 1);
            CP_COMMIT();
        }
#pragma unroll
        for (int ks = 0; ks < 2; ks++) {
            int kc = ks * 16 + lcol;
            uint32_t ah[2][4], al[2][4];
#pragma unroll
            for (int mt = 0; mt < 2; mt++) {
                int r = warp_m * 32 + mt * 16 + lrow;
                uint32_t addr = sb + buf * TSB + ((uint32_t)r * 40 + kc) * 2;
                ldsm4(ah[mt], addr);
                ldsm4(al[mt], addr + OFF_AL);
            }
#pragma unroll
            for (int ng = 0; ng < 2; ng++) {
                int r = warp_n * 32 + ng * 16 + lrow;
                uint32_t baddr = sb + buf * TSB + ((uint32_t)r * 40 + kc) * 2 + OFF_BH;
                uint32_t bh[4], bl[4];
                ldsm4(bh, baddr);
                ldsm4(bl, baddr + (OFF_BL - OFF_BH));
#pragma unroll
                for (int mt = 0; mt < 2; mt++) {
                    mma16816(acc[mt][2 * ng],     ah[mt], bh[0], bh[2]);
                    mma16816(acc[mt][2 * ng],     ah[mt], bl[0], bl[2]);
                    mma16816(acc[mt][2 * ng],     al[mt], bh[0], bh[2]);
                    mma16816(acc[mt][2 * ng + 1], ah[mt], bh[1], bh[3]);
                    mma16816(acc[mt][2 * ng + 1], ah[mt], bl[1], bl[3]);
                    mma16816(acc[mt][2 * ng + 1], al[mt], bh[1], bh[3]);
                }
            }
        }
    }

    // ---- epilogue (all outputs nullable) ----
    int gi = lane >> 2;
    int ci = (lane & 3) * 2;
#pragma unroll
    for (int mt = 0; mt < 2; mt++) {
#pragma unroll
        for (int nt = 0; nt < 4; nt++) {
            float* a4 = acc[mt][nt];
            int col = n0 + warp_n * 32 + nt * 8 + ci;
            float b0 = 0.f, b1 = 0.f;
            if (bias) { b0 = __ldg(&bias[col]); b1 = __ldg(&bias[col + 1]); }
#pragma unroll
            for (int half = 0; half < 2; half++) {
                int row = m0 + warp_m * 32 + mt * 16 + gi + half * 8;
                if (row >= M) continue;
                float v0 = a4[half * 2]     + b0;
                float v1 = a4[half * 2 + 1] + b1;
                size_t o = (size_t)row * HDIM + col;
                if (addend) {
                    float2 t = *(const float2*)(addend + o);
                    v0 += t.x; v1 += t.y;
                }
                if (Cout) *(float2*)(Cout + o) = make_float2(v0, v1);
                if (Chi) {
                    __nv_bfloat16 h0, l0, h1, l1;
                    split_bf16(v0, h0, l0);
                    split_bf16(v1, h1, l1);
                    __nv_bfloat162 hv; hv.x = h0; hv.y = h1;
                    *(__nv_bfloat162*)(Chi + o) = hv;
                    if (Clo) {
                        __nv_bfloat162 lv; lv.x = l0; lv.y = l1;
                        *(__nv_bfloat162*)(Clo + o) = lv;
                    }
                }
            }
        }
    }
#undef LOAD_STAGE
}

// ---------------- small fp32 GEMM for the F1 fold (M=118) --------------------
__global__ __launch_bounds__(256, 2)
void sgemm_pair(const float* __restrict__ A, int M,
                const float* __restrict__ B0, const float* __restrict__ B1,
                float* __restrict__ C0, float* __restrict__ C1,
                const float* __restrict__ bias0, const float* __restrict__ bias1) {
    const float* B    = blockIdx.z ? B1 : B0;
    float*       C    = blockIdx.z ? C1 : C0;
    const float* bias = blockIdx.z ? bias1 : bias0;
    __shared__ float As[2][16][132];
    __shared__ float Bs[2][16][128];
    int tid = threadIdx.x;
    int m0 = blockIdx.x * 128;
    int n0 = blockIdx.y * 128;
    int tx = tid & 15, ty = tid >> 4;
    int ar = tid >> 2;
    int ac = (tid & 3) * 4;
    int bk = tid >> 5;
    int bn = (tid & 31) * 4;
    bool aval0 = (m0 + ar) < M;
    bool aval1 = (m0 + ar + 64) < M;
    const float* Arow0 = A + (size_t)(m0 + ar) * HDIM + ac;
    const float* Arow1 = A + (size_t)(m0 + ar + 64) * HDIM + ac;
    const float* Bp0 = B + (size_t)bk * HDIM + n0 + bn;
    const float* Bp1 = B + (size_t)(bk + 8) * HDIM + n0 + bn;
    float4 af0, af1, bf0, bf1;
    const float4 fz = make_float4(0.f, 0.f, 0.f, 0.f);
#define LOADG(k0) do { \
        af0 = aval0 ? *(const float4*)(Arow0 + (k0)) : fz; \
        af1 = aval1 ? *(const float4*)(Arow1 + (k0)) : fz; \
        bf0 = *(const float4*)(Bp0 + (size_t)(k0) * HDIM); \
        bf1 = *(const float4*)(Bp1 + (size_t)(k0) * HDIM); } while (0)
#define STORES(bufi) do { \
        As[bufi][ac + 0][ar] = af0.x; As[bufi][ac + 1][ar] = af0.y; \
        As[bufi][ac + 2][ar] = af0.z; As[bufi][ac + 3][ar] = af0.w; \
        As[bufi][ac + 0][ar + 64] = af1.x; As[bufi][ac + 1][ar + 64] = af1.y; \
        As[bufi][ac + 2][ar + 64] = af1.z; As[bufi][ac + 3][ar + 64] = af1.w; \
        *(float4*)&Bs[bufi][bk][bn] = bf0; *(float4*)&Bs[bufi][bk + 8][bn] = bf1; } while (0)
    float acc[8][8];
#pragma unroll
    for (int i = 0; i < 8; i++)
#pragma unroll
        for (int j = 0; j < 8; j++) acc[i][j] = 0.f;
    LOADG(0);
    STORES(0);
    __syncthreads();
    int buf = 0;
#pragma unroll 1
    for (int kt = 0; kt < 16; kt++) {
        if (kt < 15) LOADG((kt + 1) * 16);
#pragma unroll
        for (int k = 0; k < 16; k++) {
            float4 a0 = *(const float4*)&As[buf][k][ty * 8];
            float4 a1 = *(const float4*)&As[buf][k][ty * 8 + 4];
            float4 b0 = *(const float4*)&Bs[buf][k][tx * 8];
            float4 b1 = *(const float4*)&Bs[buf][k][tx * 8 + 4];
            float a[8] = {a0.x, a0.y, a0.z, a0.w, a1.x, a1.y, a1.z, a1.w};
            float b[8] = {b0.x, b0.y, b0.z, b0.w, b1.x, b1.y, b1.z, b1.w};
#pragma unroll
            for (int i = 0; i < 8; i++)
#pragma unroll
                for (int j = 0; j < 8; j++)
                    acc[i][j] += a[i] * b[j];
        }
        if (kt < 15) { STORES(buf ^ 1); __syncthreads(); buf ^= 1; }
    }
    float bv[8];
#pragma unroll
    for (int j = 0; j < 8; j++) bv[j] = bias ? bias[n0 + tx * 8 + j] : 0.f;
#pragma unroll
    for (int i = 0; i < 8; i++) {
        int mm = m0 + ty * 8 + i;
        if (mm >= M) continue;
        float* Cp = C + (size_t)mm * HDIM + n0 + tx * 8;
        *(float4*)Cp = make_float4(acc[i][0] + bv[0], acc[i][1] + bv[1],
                                   acc[i][2] + bv[2], acc[i][3] + bv[3]);
        *(float4*)(Cp + 4) = make_float4(acc[i][4] + bv[4], acc[i][5] + bv[5],
                                         acc[i][6] + bv[6], acc[i][7] + bv[7]);
    }
#undef LOADG
#undef STORES
}

// ---------------- launcher ---------------------------------------------------
extern "C" void kernel_launch(void* const* d_in, const int* in_sizes, int n_in,
                              void* d_out, int out_size) {
    const float* atomic_num = (const float*)d_in[0];
    const float* coord      = (const float*)d_in[1];
    const float* radius     = (const float*)d_in[2];
    const int*   src        = (const int*)  d_in[3];
    const int*   dst        = (const int*)  d_in[4];
    const int*   abs_mask   = (const int*)  d_in[5];
    const int*   graph_id   = (const int*)  d_in[6];
    const float* W_atom     = (const float*)d_in[7];
    const float* b_atom     = (const float*)d_in[8];
    const float* W_coord    = (const float*)d_in[9];
    const float* b_coord    = (const float*)d_in[10];
    const float* W_node     = (const float*)d_in[11];
    const float* b_node     = (const float*)d_in[12];
    const float* W_edge     = (const float*)d_in[13];
    const float* b_edge     = (const float*)d_in[14];
    const float* W_agg      = (const float*)d_in[15];
    const float* b_agg      = (const float*)d_in[16];
    const float* W_glu_a    = (const float*)d_in[17];
    const float* b_glu_a    = (const float*)d_in[18];
    const float* W_glu_b    = (const float*)d_in[19];
    const float* b_glu_b    = (const float*)d_in[20];
    const float* exp_l      = (const float*)d_in[21];
    const float* eps_l      = (const float*)d_in[22];
    const float* W_mlp      = (const float*)d_in[23];
    const float* b_mlp      = (const float*)d_in[24];
    float* out = (float*)d_out;

    int N = in_sizes[5];
    int E = in_sizes[2];

    float *p_h, *p_hs, *p_hd, *p_F1;
    __nv_bfloat16 *p_xh, *p_xl, *p_hh, *p_hl, *p_rh, *p_rl, *p_sh, *p_Bh, *p_Bl, *p_Fh, *p_Fl;
    cudaGetSymbolAddress((void**)&p_h,   g_h);
    cudaGetSymbolAddress((void**)&p_hs,  g_hs);
    cudaGetSymbolAddress((void**)&p_hd,  g_hd);
    cudaGetSymbolAddress((void**)&p_F1,  g_F1);
    cudaGetSymbolAddress((void**)&p_xh,  g_xa_hi);
    cudaGetSymbolAddress((void**)&p_xl,  g_xa_lo);
    cudaGetSymbolAddress((void**)&p_hh,  g_h_hi);
    cudaGetSymbolAddress((void**)&p_hl,  g_h_lo);
    cudaGetSymbolAddress((void**)&p_rh,  g_r_hi);
    cudaGetSymbolAddress((void**)&p_rl,  g_r_lo);
    cudaGetSymbolAddress((void**)&p_sh,  g_s_hi);
    cudaGetSymbolAddress((void**)&p_Bh,  g_Bt_hi);
    cudaGetSymbolAddress((void**)&p_Bl,  g_Bt_lo);
    cudaGetSymbolAddress((void**)&p_Fh,  g_F1t_hi);
    cudaGetSymbolAddress((void**)&p_Fl,  g_F1t_lo);

    const int MMA_SMEM = 81920;
    cudaFuncSetAttribute(mma_gemm, cudaFuncAttributeMaxDynamicSharedMemorySize, MMA_SMEM);

    int mtiles = (N + 127) / 128;
    int eb = (E + 255) / 256;
    int nhb = (N * HDIM + 255) / 256;
    int aggb = (N + 7) / 8;

    // CSR build
    zero_pre_kernel<<<80, 256>>>(N);
    hist_kernel<<<eb, 256>>>(dst, E);
    scan_kernel<<<1, 1024>>>(N);
    fill_kernel<<<eb, 256>>>(dst, E);

    // folds + conversions
    sgemm_pair<<<dim3(1, 2, 1), 256>>>(W_atom, ATOMD, W_node, W_node, p_F1, p_F1,
                                       nullptr, nullptr);
    fold_small_kernel<<<1, HDIM>>>(W_coord, W_node, b_atom, b_coord, b_node);
    coord_init_kernel<<<nhb, 256>>>(coord, N);
    conv_x_kernel<<<(N * 128 + 255) / 256, 256>>>(atomic_num, N);
    conv_F1t_kernel<<<(HDIM * 128 + 255) / 256, 256>>>();
    conv_wT_kernel<<<dim3(HH / 256, 8, 1), 256>>>(W_agg, W_glu_a, W_glu_b);
    uv_kernel<<<2, HDIM>>>(W_agg, W_edge, b_edge, b_agg);

    // init: h = x@F1 + coordpart; write h fp32 + hi/lo
    mma_gemm<<<dim3(mtiles, 2, 1), 512, MMA_SMEM>>>(
        p_xh, p_xl, N, 128, p_Fh, p_Fl, p_Fh, p_Fl,
        p_h, p_h, nullptr, nullptr, p_hd,
        p_hh, p_hl, p_hh, p_hl);

    for (int l = 0; l < 2; l++) {
        // z=0: hs (bf16 hi only, for gather); z=1: hd (fp32 only)
        mma_gemm<<<dim3(mtiles, 2, 2), 512, MMA_SMEM>>>(
            p_hh, p_hl, N, HDIM,
            p_Bh + (size_t)(2 * l) * HH,     p_Bl + (size_t)(2 * l) * HH,
            p_Bh + (size_t)(2 * l + 1) * HH, p_Bl + (size_t)(2 * l + 1) * HH,
            nullptr, p_hd, nullptr, nullptr, nullptr,
            p_sh, nullptr, nullptr, nullptr);
        agg_kernel<<<aggb, 256>>>(src, radius, exp_l, eps_l, l, N);
        // z=0: ga (fp32); z=1: gb (fp32)
        mma_gemm<<<dim3(mtiles, 2, 2), 512, MMA_SMEM>>>(
            p_rh, p_rl, N, HDIM,
            p_Bh + (size_t)(4 + 2 * l) * HH, p_Bl + (size_t)(4 + 2 * l) * HH,
            p_Bh + (size_t)(5 + 2 * l) * HH, p_Bl + (size_t)(5 + 2 * l) * HH,
            p_hs, p_hd, b_glu_a + l * HDIM, b_glu_b + l * HDIM, nullptr,
            nullptr, nullptr, nullptr, nullptr);
        if (l == 0) glu_kernel<<<nhb, 256>>>(N);
    }

    // fused last-layer GLU + masked segment-sum, then MLP head
    glu_segsum_kernel<<<(N + 127) / 128, HDIM>>>(abs_mask, graph_id, N);
    mlp_kernel<<<GN, 128>>>(W_mlp, b_mlp, out, 1.0f / (float)N);
}